// round 8
// baseline (speedup 1.0000x reference)
#include <cuda_runtime.h>
#include <cstdint>

#define D_MODEL 1024
#define NHEAD   16
#define HDIM    64
#define BATCH   2
#define SEQ     2048
#define MTOT    (BATCH*SEQ)          // 4096
#define NQKV    (3*D_MODEL)          // 3072

// ---------------- scratch (static device globals; no allocation) ----------
__device__ float g_q[BATCH*NHEAD*HDIM*SEQ];     // [B,H,Dh,T]  (tf32-rounded)
__device__ float g_k[BATCH*NHEAD*HDIM*SEQ];     // [B,H,Dh,T]  (tf32-rounded)
__device__ float g_v[BATCH*NHEAD*SEQ*HDIM];     // [B,H,T,Dh]  (tf32-rounded)
__device__ float g_attn[MTOT*D_MODEL];          // [B,T,C]     (tf32-rounded)
__device__ float g_xr[MTOT*D_MODEL];            // x, tf32-rounded
__device__ float g_wqkvr[D_MODEL*NQKV];         // w_qkv, tf32-rounded
__device__ float g_woutr[D_MODEL*D_MODEL];      // w_out, tf32-rounded

// ---------------- helpers ---------------------------------------------------
__device__ __forceinline__ uint32_t smem_u32(const void* p) {
    uint32_t a;
    asm("{ .reg .u64 t; cvta.to.shared.u64 t, %1; cvt.u32.u64 %0, t; }" : "=r"(a) : "l"(p));
    return a;
}
__device__ __forceinline__ uint32_t f2tf(float x) {
    uint32_t r; asm("cvt.rna.tf32.f32 %0, %1;" : "=r"(r) : "f"(x)); return r;
}
__device__ __forceinline__ float ftf(float x) { return __uint_as_float(f2tf(x)); }
__device__ __forceinline__ uint4 cvt4s(float4 v, float s) {
    return make_uint4(f2tf(v.x*s), f2tf(v.y*s), f2tf(v.z*s), f2tf(v.w*s));
}
__device__ __forceinline__ void mma8(float* c,
    uint32_t a0, uint32_t a1, uint32_t a2, uint32_t a3,
    uint32_t b0, uint32_t b1)
{
    asm volatile(
        "mma.sync.aligned.m16n8k8.row.col.f32.tf32.tf32.f32 "
        "{%0,%1,%2,%3}, {%4,%5,%6,%7}, {%8,%9}, {%0,%1,%2,%3};"
        : "+f"(c[0]), "+f"(c[1]), "+f"(c[2]), "+f"(c[3])
        : "r"(a0), "r"(a1), "r"(a2), "r"(a3), "r"(b0), "r"(b1));
}
__device__ __forceinline__ void cp16(uint32_t dst, const void* src) {
    asm volatile("cp.async.cg.shared.global [%0], [%1], 16;" :: "r"(dst), "l"(src));
}
#define CP_COMMIT() asm volatile("cp.async.commit_group;" ::: "memory")
#define CP_WAIT(n)  asm volatile("cp.async.wait_group %0;" :: "n"(n) : "memory")

// ---- tf32 rounding pre-pass ------------------------------------------------
__global__ __launch_bounds__(256) void round_tf32_kernel(
    const float4* __restrict__ src, float4* __restrict__ dst, int n4)
{
    int i = blockIdx.x*blockDim.x + threadIdx.x;
    if (i < n4) {
        float4 v = src[i];
        dst[i] = make_float4(ftf(v.x), ftf(v.y), ftf(v.z), ftf(v.w));
    }
}

// ===========================================================================
// tf32 MMA GEMM, 4-stage cp.async pipeline. CTA tile 128x128, 256 threads
// (8 warps, warp tile 64x32). K chunk 16. Inputs pre-rounded (rna) in gmem.
// sA stage: [128][20]  (2560 words);  sB stage: [16][136] (2176 words).
// ===========================================================================
#define SA_ST 2560
#define SB_ST 2176
#define SB_BASE (4*SA_ST)            // 10240
#define GEMM_SMEM_WORDS (4*SA_ST + 4*SB_ST)    // 18944
#define GEMM_SMEM_BYTES (GEMM_SMEM_WORDS*4)    // 75776

__device__ __forceinline__ void gemm_issue_stage(
    uint32_t smem_u, int st,
    const float* __restrict__ A, const float* __restrict__ W, int ldW,
    int m0, int n0, int k0, int tid)
{
    uint32_t sa = smem_u + (st*SA_ST)*4;
    uint32_t sb = smem_u + (SB_BASE + st*SB_ST)*4;
    #pragma unroll
    for (int i = 0; i < 2; i++) {
        int idx = tid + i*256;
        int row = idx >> 2, c4 = (idx & 3)*4;
        cp16(sa + (row*20 + c4)*4, A + (size_t)(m0+row)*D_MODEL + k0 + c4);
    }
    #pragma unroll
    for (int i = 0; i < 2; i++) {
        int idx = tid + i*256;
        int r = idx >> 5, c = (idx & 31)*4;
        cp16(sb + (r*136 + c)*4, W + (size_t)(k0+r)*ldW + n0 + c);
    }
}

__device__ __forceinline__ void gemm_tile_cp(
    uint32_t* sm, uint32_t smem_u,
    const float* __restrict__ A, const float* __restrict__ W, int ldW,
    int m0, int n0, float acc[4][4][4])
{
    const int tid  = threadIdx.x;
    const int lane = tid & 31;
    const int wid  = tid >> 5;
    const int wm   = wid & 1;      // rows 0/64
    const int wn   = wid >> 1;     // 0..3, cols of 32
    const int lq   = lane & 3;
    const int gq   = lane >> 2;

    gemm_issue_stage(smem_u, 0, A, W, ldW, m0, n0, 0,  tid); CP_COMMIT();
    gemm_issue_stage(smem_u, 1, A, W, ldW, m0, n0, 16, tid); CP_COMMIT();
    gemm_issue_stage(smem_u, 2, A, W, ldW, m0, n0, 32, tid); CP_COMMIT();

    for (int s = 0; s < 64; s++) {
        CP_WAIT(2);
        __syncthreads();
        if (s + 3 < 64) {
            gemm_issue_stage(smem_u, (s+3)&3, A, W, ldW, m0, n0, (s+3)*16, tid);
            CP_COMMIT();
        }
        const uint32_t* bufA = sm + (s&3)*SA_ST;
        const uint32_t* bufB = sm + SB_BASE + (s&3)*SB_ST;

        #pragma unroll
        for (int kk = 0; kk < 2; kk++) {
            const int kb = kk*8 + lq;
            uint32_t a[4][4];
            #pragma unroll
            for (int mt = 0; mt < 4; mt++) {
                int r = wm*64 + mt*16 + gq;
                a[mt][0] = bufA[ r      *20 + kb    ];
                a[mt][1] = bufA[(r + 8) *20 + kb    ];
                a[mt][2] = bufA[ r      *20 + kb + 4];
                a[mt][3] = bufA[(r + 8) *20 + kb + 4];
            }
            #pragma unroll
            for (int nt = 0; nt < 4; nt++) {
                int nb = wn*32 + nt*8 + gq;
                uint32_t b0 = bufB[ kb      *136 + nb];
                uint32_t b1 = bufB[(kb + 4) *136 + nb];
                #pragma unroll
                for (int mt = 0; mt < 4; mt++)
                    mma8(acc[mt][nt], a[mt][0], a[mt][1], a[mt][2], a[mt][3], b0, b1);
            }
        }
    }
}

// ---- GEMM 1: qkv = x @ w_qkv + b, scatter q/k transposed (rounded) --------
__global__ __launch_bounds__(256,2) void qkv_mma_kernel(const float* __restrict__ bias)
{
    extern __shared__ uint32_t smg[];
    uint32_t smem_u = smem_u32(smg);

    const int n0 = blockIdx.x * 128;
    const int m0 = blockIdx.y * 128;
    const int lane = threadIdx.x & 31;
    const int wid  = threadIdx.x >> 5;
    const int wm = wid & 1, wn = wid >> 1;
    const int lq = lane & 3, gq = lane >> 2;

    float acc[4][4][4];
    #pragma unroll
    for (int i = 0; i < 4; i++)
        #pragma unroll
        for (int j = 0; j < 4; j++)
            #pragma unroll
            for (int k = 0; k < 4; k++) acc[i][j][k] = 0.f;

    gemm_tile_cp(smg, smem_u, g_xr, g_wqkvr, NQKV, m0, n0, acc);

    #pragma unroll
    for (int mt = 0; mt < 4; mt++) {
        int rbase = m0 + wm*64 + mt*16 + gq;
        #pragma unroll
        for (int half = 0; half < 2; half++) {
            int row = rbase + half*8;
            int bb = row >> 11;
            int t  = row & 2047;
            #pragma unroll
            for (int nt = 0; nt < 4; nt++) {
                int n = n0 + wn*32 + nt*8 + lq*2;
                float v0 = ftf(acc[mt][nt][half*2+0] + __ldg(bias + n));
                float v1 = ftf(acc[mt][nt][half*2+1] + __ldg(bias + n + 1));
                int sec = n >> 10;
                int h   = (n >> 6) & 15;
                int d   = n & 63;
                int bh  = bb*NHEAD + h;
                if (sec == 2) {
                    *(float2*)&g_v[((size_t)bh*SEQ + t)*HDIM + d] = make_float2(v0, v1);
                } else {
                    float* p = sec ? g_k : g_q;
                    p[((size_t)bh*HDIM + d    )*SEQ + t] = v0;
                    p[((size_t)bh*HDIM + d + 1)*SEQ + t] = v1;
                }
            }
        }
    }
}

// ---- GEMM 3: out = attn @ w_out + b ----------------------------------------
__global__ __launch_bounds__(256,2) void out_mma_kernel(
    const float* __restrict__ bias, float* __restrict__ out)
{
    extern __shared__ uint32_t smg[];
    uint32_t smem_u = smem_u32(smg);

    const int n0 = blockIdx.x * 128;
    const int m0 = blockIdx.y * 128;
    const int lane = threadIdx.x & 31;
    const int wid  = threadIdx.x >> 5;
    const int wm = wid & 1, wn = wid >> 1;
    const int lq = lane & 3, gq = lane >> 2;

    float acc[4][4][4];
    #pragma unroll
    for (int i = 0; i < 4; i++)
        #pragma unroll
        for (int j = 0; j < 4; j++)
            #pragma unroll
            for (int k = 0; k < 4; k++) acc[i][j][k] = 0.f;

    gemm_tile_cp(smg, smem_u, g_attn, g_woutr, D_MODEL, m0, n0, acc);

    #pragma unroll
    for (int mt = 0; mt < 4; mt++) {
        int rbase = m0 + wm*64 + mt*16 + gq;
        #pragma unroll
        for (int half = 0; half < 2; half++) {
            int row = rbase + half*8;
            #pragma unroll
            for (int nt = 0; nt < 4; nt++) {
                int n = n0 + wn*32 + nt*8 + lq*2;
                float v0 = acc[mt][nt][half*2+0] + __ldg(bias + n);
                float v1 = acc[mt][nt][half*2+1] + __ldg(bias + n + 1);
                *(float2*)&out[(size_t)row*D_MODEL + n] = make_float2(v0, v1);
            }
        }
    }
}

// ===========================================================================
// Flash attention, tf32 MMA, cp.async 3-buffer K/V pipeline, P via shuffles.
// QTILE=128 rows/CTA, KTILE=64, 8 warps (warp owns 16 rows).
// K/V in gmem are already tf32-rounded (qkv epilogue).
#define QTILE 128
#define KTILE 64
#define KVSTR 72
#define KBUF 4608
#define BUF_WORDS 9216
#define FLASH_SMEM_WORDS (3*BUF_WORDS)          // 27648
#define FLASH_SMEM_BYTES (FLASH_SMEM_WORDS*4)   // 110592
#define QS_OFF (2*BUF_WORDS)                    // Qs overlays buffer 2

__device__ __forceinline__ void flash_issue_kv(
    uint32_t smem_u, int bufidx, int kt,
    const float* __restrict__ kT, const float* __restrict__ vb, int tid)
{
    uint32_t kb = smem_u + (bufidx*BUF_WORDS)*4;
    uint32_t vbuf = kb + KBUF*4;
    const int rhi = tid >> 4;          // 0..15
    const int c16 = (tid & 15)*4;      // 0..60
    #pragma unroll
    for (int i = 0; i < 4; i++) {
        int d = i*16 + rhi;
        cp16(kb + (d*KVSTR + c16)*4, kT + (size_t)d*SEQ + kt*KTILE + c16);
    }
    #pragma unroll
    for (int i = 0; i < 4; i++) {
        int c = i*16 + rhi;
        cp16(vbuf + (c*KVSTR + c16)*4, vb + (size_t)(kt*KTILE + c)*HDIM + c16);
    }
}

__global__ __launch_bounds__(256,2) void flash_mma_kernel()
{
    extern __shared__ uint32_t smu[];
    uint32_t smem_u = smem_u32(smu);
    uint32_t* Qs = smu + QS_OFF;        // [d][t] stride 132, prologue only

    const int tid  = threadIdx.x;
    const int lane = tid & 31;
    const int wid  = tid >> 5;
    const int lq   = lane & 3;
    const int gq   = lane >> 2;
    const int r0   = wid * 16;
    const int psrc = (lane & 28) | (lq >> 1);
    const int odd  = lq & 1;

    const int qt = blockIdx.x;
    const int h  = blockIdx.y;
    const int bb = blockIdx.z;
    const int bh = bb*NHEAD + h;

    const float* qT = g_q + (size_t)bh*HDIM*SEQ + qt*QTILE;
    const float* kT = g_k + (size_t)bh*HDIM*SEQ;
    const float* vb = g_v + (size_t)bh*SEQ*HDIM;

    flash_issue_kv(smem_u, 0, 0, kT, vb, tid); CP_COMMIT();
    flash_issue_kv(smem_u, 1, 1, kT, vb, tid); CP_COMMIT();

    const float scale = 0.125f * 1.4426950408889634f;   // base-2 softmax

    for (int i = tid; i < 64*32; i += 256) {
        int d = i >> 5, t4 = i & 31;
        float4 v = *(const float4*)(qT + (size_t)d*SEQ + t4*4);
        *(uint4*)&Qs[d*132 + t4*4] = cvt4s(v, scale);
    }
    __syncthreads();

    const int row0 = r0 + gq;
    const int row1 = row0 + 8;

    uint32_t qa[8][4];
    #pragma unroll
    for (int kk = 0; kk < 8; kk++) {
        int kb = kk*8 + lq;
        qa[kk][0] = Qs[ kb     *132 + row0];
        qa[kk][1] = Qs[ kb     *132 + row1];
        qa[kk][2] = Qs[(kb + 4)*132 + row0];
        qa[kk][3] = Qs[(kb + 4)*132 + row1];
    }

    float m0 = -1e30f, m1 = -1e30f, l0 = 0.f, l1 = 0.f;
    float o[8][4];
    #pragma unroll
    for (int i = 0; i < 8; i++)
        #pragma unroll
        for (int j = 0; j < 4; j++) o[i][j] = 0.f;

    for (int kt = 0; kt < SEQ/KTILE; kt++) {
        CP_WAIT(1);
        __syncthreads();
        if (kt + 2 < SEQ/KTILE) {
            flash_issue_kv(smem_u, (kt+2)%3, kt+2, kT, vb, tid);
            CP_COMMIT();
        }
        const uint32_t* Kb = smu + (kt%3)*BUF_WORDS;
        const uint32_t* Vb = Kb + KBUF;

        float s[8][4];
        #pragma unroll
        for (int nt = 0; nt < 8; nt++)
            #pragma unroll
            for (int j = 0; j < 4; j++) s[nt][j] = 0.f;

        #pragma unroll
        for (int kk = 0; kk < 8; kk++) {
            int kb = kk*8 + lq;
            #pragma unroll
            for (int nt = 0; nt < 8; nt++) {
                uint32_t b0 = Kb[ kb     *KVSTR + nt*8 + gq];
                uint32_t b1 = Kb[(kb + 4)*KVSTR + nt*8 + gq];
                mma8(s[nt], qa[kk][0], qa[kk][1], qa[kk][2], qa[kk][3], b0, b1);
            }
        }

        float mt0 = -1e30f, mt1 = -1e30f;
        #pragma unroll
        for (int nt = 0; nt < 8; nt++) {
            mt0 = fmaxf(mt0, fmaxf(s[nt][0], s[nt][1]));
            mt1 = fmaxf(mt1, fmaxf(s[nt][2], s[nt][3]));
        }
        mt0 = fmaxf(mt0, __shfl_xor_sync(0xffffffffu, mt0, 1));
        mt0 = fmaxf(mt0, __shfl_xor_sync(0xffffffffu, mt0, 2));
        mt1 = fmaxf(mt1, __shfl_xor_sync(0xffffffffu, mt1, 1));
        mt1 = fmaxf(mt1, __shfl_xor_sync(0xffffffffu, mt1, 2));

        float mn0 = fmaxf(m0, mt0);
        float mn1 = fmaxf(m1, mt1);
        float corr0 = exp2f(m0 - mn0);
        float corr1 = exp2f(m1 - mn1);
        m0 = mn0; m1 = mn1;

        uint32_t pu[8][4];
        float sum0 = 0.f, sum1 = 0.f;
        #pragma unroll
        for (int nt = 0; nt < 8; nt++) {
            float p0 = exp2f(s[nt][0] - mn0);
            float p1 = exp2f(s[nt][1] - mn0);
            float p2 = exp2f(s[nt][2] - mn1);
            float p3 = exp2f(s[nt][3] - mn1);
            sum0 += p0 + p1;
            sum1 += p2 + p3;
            pu[nt][0] = f2tf(p0); pu[nt][1] = f2tf(p1);
            pu[nt][2] = f2tf(p2); pu[nt][3] = f2tf(p3);
        }
        sum0 += __shfl_xor_sync(0xffffffffu, sum0, 1);
        sum0 += __shfl_xor_sync(0xffffffffu, sum0, 2);
        sum1 += __shfl_xor_sync(0xffffffffu, sum1, 1);
        sum1 += __shfl_xor_sync(0xffffffffu, sum1, 2);
        l0 = l0*corr0 + sum0;
        l1 = l1*corr1 + sum1;

        #pragma unroll
        for (int nt = 0; nt < 8; nt++) {
            o[nt][0] *= corr0; o[nt][1] *= corr0;
            o[nt][2] *= corr1; o[nt][3] *= corr1;
        }

        #pragma unroll
        for (int kk = 0; kk < 8; kk++) {
            uint32_t v0 = __shfl_sync(0xffffffffu, pu[kk][0], psrc);
            uint32_t v1 = __shfl_sync(0xffffffffu, pu[kk][1], psrc);
            uint32_t w0 = __shfl_sync(0xffffffffu, pu[kk][2], psrc);
            uint32_t w1 = __shfl_sync(0xffffffffu, pu[kk][3], psrc);
            uint32_t u0 = __shfl_sync(0xffffffffu, pu[kk][0], psrc + 2);
            uint32_t u1 = __shfl_sync(0xffffffffu, pu[kk][1], psrc + 2);
            uint32_t x0 = __shfl_sync(0xffffffffu, pu[kk][2], psrc + 2);
            uint32_t x1 = __shfl_sync(0xffffffffu, pu[kk][3], psrc + 2);
            uint32_t a0 = odd ? v1 : v0;
            uint32_t a1 = odd ? w1 : w0;
            uint32_t a2 = odd ? u1 : u0;
            uint32_t a3 = odd ? x1 : x0;
            int kb = kk*8 + lq;
            #pragma unroll
            for (int nt = 0; nt < 8; nt++) {
                uint32_t b0 = Vb[ kb     *KVSTR + nt*8 + gq];
                uint32_t b1 = Vb[(kb + 4)*KVSTR + nt*8 + gq];
                mma8(o[nt], a0, a1, a2, a3, b0, b1);
            }
        }
    }

    float inv0 = 1.0f / l0;
    float inv1 = 1.0f / l1;
    #pragma unroll
    for (int nt = 0; nt < 8; nt++) {
        int d = nt*8 + lq*2;
        float* dst0 = g_attn + (size_t)(bb*SEQ + qt*QTILE + row0)*D_MODEL + h*64 + d;
        float* dst1 = g_attn + (size_t)(bb*SEQ + qt*QTILE + row1)*D_MODEL + h*64 + d;
        *(float2*)dst0 = make_float2(ftf(o[nt][0]*inv0), ftf(o[nt][1]*inv0));
        *(float2*)dst1 = make_float2(ftf(o[nt][2]*inv1), ftf(o[nt][3]*inv1));
    }
}

// ===========================================================================
extern "C" void kernel_launch(void* const* d_in, const int* in_sizes, int n_in,
                              void* d_out, int out_size)
{
    const float* x     = (const float*)d_in[0];
    const float* w_qkv = (const float*)d_in[1];
    const float* b_qkv = (const float*)d_in[2];
    const float* w_out = (const float*)d_in[3];
    const float* b_out = (const float*)d_in[4];
    float* out = (float*)d_out;

    (void)in_sizes; (void)n_in; (void)out_size;

    cudaFuncSetAttribute(qkv_mma_kernel,
                         cudaFuncAttributeMaxDynamicSharedMemorySize, GEMM_SMEM_BYTES);
    cudaFuncSetAttribute(out_mma_kernel,
                         cudaFuncAttributeMaxDynamicSharedMemorySize, GEMM_SMEM_BYTES);
    cudaFuncSetAttribute(flash_mma_kernel,
                         cudaFuncAttributeMaxDynamicSharedMemorySize, FLASH_SMEM_BYTES);

    float* xr;    cudaGetSymbolAddress((void**)&xr,    g_xr);
    float* wqkvr; cudaGetSymbolAddress((void**)&wqkvr, g_wqkvr);
    float* woutr; cudaGetSymbolAddress((void**)&woutr, g_woutr);

    // 0) tf32-round inputs (rna) into scratch
    round_tf32_kernel<<<(MTOT*D_MODEL/4 + 255)/256, 256>>>(
        (const float4*)x, (float4*)xr, MTOT*D_MODEL/4);
    round_tf32_kernel<<<(D_MODEL*NQKV/4 + 255)/256, 256>>>(
        (const float4*)w_qkv, (float4*)wqkvr, D_MODEL*NQKV/4);
    round_tf32_kernel<<<(D_MODEL*D_MODEL/4 + 255)/256, 256>>>(
        (const float4*)w_out, (float4*)woutr, D_MODEL*D_MODEL/4);

    // 1) QKV GEMM (tf32 MMA, cp.async) + bias + rounded scatter
    {
        dim3 grid(NQKV/128, MTOT/128);    // (24, 32)
        qkv_mma_kernel<<<grid, 256, GEMM_SMEM_BYTES>>>(b_qkv);
    }
    // 2) flash attention (tf32 MMA, cp.async)
    {
        dim3 grid(SEQ/QTILE, NHEAD, BATCH); // (16, 16, 2)
        flash_mma_kernel<<<grid, 256, FLASH_SMEM_BYTES>>>();
    }
    // 3) out GEMM (tf32 MMA, cp.async) + bias
    {
        dim3 grid(D_MODEL/128, MTOT/128); // (8, 32)
        out_mma_kernel<<<grid, 256, GEMM_SMEM_BYTES>>>(b_out, out);
    }
}

// round 9
// speedup vs baseline: 1.7802x; 1.7802x over previous
#include <cuda_runtime.h>
#include <cuda_fp16.h>
#include <cstdint>

#define D_MODEL 1024
#define NHEAD   16
#define HDIM    64
#define BATCH   2
#define SEQ     2048
#define MTOT    (BATCH*SEQ)          // 4096
#define NQKV    (3*D_MODEL)          // 3072

// ---------------- scratch (static device globals; no allocation) ----------
__device__ __half g_qh[BATCH*NHEAD*SEQ*HDIM];    // [B,H,T,Dh]  pre-scaled
__device__ __half g_kh[BATCH*NHEAD*SEQ*HDIM];    // [B,H,T,Dh]
__device__ __half g_vT[BATCH*NHEAD*HDIM*SEQ];    // [B,H,Dh,T]  (transposed)
__device__ __half g_attnh[MTOT*D_MODEL];         // [B,T,C]
__device__ __half g_xh[MTOT*D_MODEL];            // x as half
__device__ __half g_wqkvT[NQKV*D_MODEL];         // w_qkv^T as half [3072][1024]
__device__ __half g_woutT[D_MODEL*D_MODEL];      // w_out^T as half [1024][1024]

// ---------------- helpers ---------------------------------------------------
__device__ __forceinline__ uint32_t smem_u32(const void* p) {
    uint32_t a;
    asm("{ .reg .u64 t; cvta.to.shared.u64 t, %1; cvt.u32.u64 %0, t; }" : "=r"(a) : "l"(p));
    return a;
}
__device__ __forceinline__ uint32_t h2pack(float lo, float hi) {
    __half2 h = __floats2half2_rn(lo, hi);
    return *(uint32_t*)&h;
}
__device__ __forceinline__ void mma16(float* c,
    uint32_t a0, uint32_t a1, uint32_t a2, uint32_t a3,
    uint32_t b0, uint32_t b1)
{
    asm volatile(
        "mma.sync.aligned.m16n8k16.row.col.f32.f16.f16.f32 "
        "{%0,%1,%2,%3}, {%4,%5,%6,%7}, {%8,%9}, {%0,%1,%2,%3};"
        : "+f"(c[0]), "+f"(c[1]), "+f"(c[2]), "+f"(c[3])
        : "r"(a0), "r"(a1), "r"(a2), "r"(a3), "r"(b0), "r"(b1));
}
__device__ __forceinline__ void cp16(uint32_t dst, const void* src) {
    asm volatile("cp.async.cg.shared.global [%0], [%1], 16;" :: "r"(dst), "l"(src));
}
#define CP_COMMIT() asm volatile("cp.async.commit_group;" ::: "memory")
#define CP_WAIT(n)  asm volatile("cp.async.wait_group %0;" :: "n"(n) : "memory")

// ---- pre-pass: convert x to half -------------------------------------------
__global__ __launch_bounds__(256) void cvt_half_kernel(
    const float4* __restrict__ src, uint2* __restrict__ dst, int n4)
{
    int i = blockIdx.x*256 + threadIdx.x;
    if (i < n4) {
        float4 v = src[i];
        dst[i] = make_uint2(h2pack(v.x, v.y), h2pack(v.z, v.w));
    }
}
// ---- pre-pass: transpose + convert weights to half -------------------------
__global__ __launch_bounds__(256) void transcvt_half_kernel(
    const float* __restrict__ src, __half* __restrict__ dst, int R, int C)
{
    __shared__ float t[32][33];
    int bx = blockIdx.x * 32;   // C offset
    int by = blockIdx.y * 32;   // R offset
    int tx = threadIdx.x & 31;
    int ty = threadIdx.x >> 5;
    #pragma unroll
    for (int i = 0; i < 32; i += 8)
        t[ty + i][tx] = src[(size_t)(by + ty + i)*C + bx + tx];
    __syncthreads();
    #pragma unroll
    for (int i = 0; i < 32; i += 8)
        dst[(size_t)(bx + ty + i)*R + by + tx] = __float2half(t[tx][ty + i]);
}

// ===========================================================================
// fp16 MMA GEMM: CTA 128x128, 256 threads (8 warps, warp tile 64x32).
// K chunk 32 halves, 4-stage cp.async. A row-major [m][k], B = W^T [n][k].
// smem per stage: A 128x40 halves (80B rows) + B 128x40 halves = 20480B.
// ===========================================================================
#define G_STAGE_BYTES 20480
#define G_STAGE_WORDS 5120
#define G_ROW_WORDS 20
#define GEMM_SMEM_BYTES (4*G_STAGE_BYTES)   // 81920

__device__ __forceinline__ void gemm_issue(
    uint32_t smem_u, int st,
    const __half* __restrict__ A, const __half* __restrict__ B,
    int m0, int n0, int k0, int tid)
{
    uint32_t sa = smem_u + st*G_STAGE_BYTES;
    uint32_t sb = sa + 128*80;
    #pragma unroll
    for (int i = 0; i < 2; i++) {
        int idx = tid + i*256;
        int row = idx >> 2, c8 = idx & 3;
        cp16(sa + row*80 + c8*16, A + (size_t)(m0+row)*D_MODEL + k0 + c8*8);
    }
    #pragma unroll
    for (int i = 0; i < 2; i++) {
        int idx = tid + i*256;
        int nb = idx >> 2, c8 = idx & 3;
        cp16(sb + nb*80 + c8*16, B + (size_t)(n0+nb)*D_MODEL + k0 + c8*8);
    }
}

__device__ __forceinline__ void gemm_tile_h(
    const uint32_t* sm, uint32_t smem_u,
    const __half* __restrict__ A, const __half* __restrict__ B,
    int m0, int n0, float acc[4][4][4])
{
    const int tid  = threadIdx.x;
    const int lane = tid & 31;
    const int wid  = tid >> 5;
    const int wm   = wid & 1;
    const int wn   = wid >> 1;
    const int lq   = lane & 3;
    const int gq   = lane >> 2;

    gemm_issue(smem_u, 0, A, B, m0, n0, 0,  tid); CP_COMMIT();
    gemm_issue(smem_u, 1, A, B, m0, n0, 32, tid); CP_COMMIT();
    gemm_issue(smem_u, 2, A, B, m0, n0, 64, tid); CP_COMMIT();

    for (int s = 0; s < 32; s++) {
        CP_WAIT(2);
        __syncthreads();
        if (s + 3 < 32) {
            gemm_issue(smem_u, (s+3)&3, A, B, m0, n0, (s+3)*32, tid);
            CP_COMMIT();
        }
        const uint32_t* bufA = sm + (s&3)*G_STAGE_WORDS;
        const uint32_t* bufB = bufA + 128*G_ROW_WORDS;

        #pragma unroll
        for (int kk = 0; kk < 2; kk++) {
            const int ko = kk*8 + lq;
            uint32_t a[4][4];
            #pragma unroll
            for (int mt = 0; mt < 4; mt++) {
                int r = wm*64 + mt*16 + gq;
                a[mt][0] = bufA[ r      *G_ROW_WORDS + ko    ];
                a[mt][1] = bufA[(r + 8) *G_ROW_WORDS + ko    ];
                a[mt][2] = bufA[ r      *G_ROW_WORDS + ko + 4];
                a[mt][3] = bufA[(r + 8) *G_ROW_WORDS + ko + 4];
            }
            #pragma unroll
            for (int nt = 0; nt < 4; nt++) {
                int nb = wn*32 + nt*8 + gq;
                uint32_t b0 = bufB[nb*G_ROW_WORDS + ko];
                uint32_t b1 = bufB[nb*G_ROW_WORDS + ko + 4];
                #pragma unroll
                for (int mt = 0; mt < 4; mt++)
                    mma16(acc[mt][nt], a[mt][0], a[mt][1], a[mt][2], a[mt][3], b0, b1);
            }
        }
    }
}

// ---- GEMM 1: qkv = x @ w_qkv + b, scatter to half q(scaled)/k/vT -----------
__global__ __launch_bounds__(256,2) void qkv_mma_kernel(const float* __restrict__ bias)
{
    extern __shared__ uint32_t smg[];
    uint32_t smem_u = smem_u32(smg);

    const int n0 = blockIdx.x * 128;
    const int m0 = blockIdx.y * 128;
    const int lane = threadIdx.x & 31;
    const int wid  = threadIdx.x >> 5;
    const int wm = wid & 1, wn = wid >> 1;
    const int lq = lane & 3, gq = lane >> 2;

    float acc[4][4][4];
    #pragma unroll
    for (int i = 0; i < 4; i++)
        #pragma unroll
        for (int j = 0; j < 4; j++)
            #pragma unroll
            for (int k = 0; k < 4; k++) acc[i][j][k] = 0.f;

    gemm_tile_h(smg, smem_u, g_xh, g_wqkvT, m0, n0, acc);

    const float QSCALE = 0.125f * 1.4426950408889634f;   // 1/sqrt(Dh) * log2(e)

    #pragma unroll
    for (int mt = 0; mt < 4; mt++) {
        int rbase = m0 + wm*64 + mt*16 + gq;
        #pragma unroll
        for (int half_ = 0; half_ < 2; half_++) {
            int row = rbase + half_*8;
            int bb = row >> 11;
            int t  = row & 2047;
            #pragma unroll
            for (int nt = 0; nt < 4; nt++) {
                int n = n0 + wn*32 + nt*8 + lq*2;
                float v0 = acc[mt][nt][half_*2+0] + __ldg(bias + n);
                float v1 = acc[mt][nt][half_*2+1] + __ldg(bias + n + 1);
                int sec = n >> 10;
                int h   = (n >> 6) & 15;
                int d   = n & 63;
                int bh  = bb*NHEAD + h;
                if (sec == 0) {
                    *(uint32_t*)&g_qh[((size_t)bh*SEQ + t)*HDIM + d] =
                        h2pack(v0*QSCALE, v1*QSCALE);
                } else if (sec == 1) {
                    *(uint32_t*)&g_kh[((size_t)bh*SEQ + t)*HDIM + d] = h2pack(v0, v1);
                } else {
                    g_vT[((size_t)bh*HDIM + d    )*SEQ + t] = __float2half(v0);
                    g_vT[((size_t)bh*HDIM + d + 1)*SEQ + t] = __float2half(v1);
                }
            }
        }
    }
}

// ---- GEMM 3: out = attn @ w_out + b (f32 output) ----------------------------
__global__ __launch_bounds__(256,2) void out_mma_kernel(
    const float* __restrict__ bias, float* __restrict__ out)
{
    extern __shared__ uint32_t smg[];
    uint32_t smem_u = smem_u32(smg);

    const int n0 = blockIdx.x * 128;
    const int m0 = blockIdx.y * 128;
    const int lane = threadIdx.x & 31;
    const int wid  = threadIdx.x >> 5;
    const int wm = wid & 1, wn = wid >> 1;
    const int lq = lane & 3, gq = lane >> 2;

    float acc[4][4][4];
    #pragma unroll
    for (int i = 0; i < 4; i++)
        #pragma unroll
        for (int j = 0; j < 4; j++)
            #pragma unroll
            for (int k = 0; k < 4; k++) acc[i][j][k] = 0.f;

    gemm_tile_h(smg, smem_u, g_attnh, g_woutT, m0, n0, acc);

    #pragma unroll
    for (int mt = 0; mt < 4; mt++) {
        int rbase = m0 + wm*64 + mt*16 + gq;
        #pragma unroll
        for (int half_ = 0; half_ < 2; half_++) {
            int row = rbase + half_*8;
            #pragma unroll
            for (int nt = 0; nt < 4; nt++) {
                int n = n0 + wn*32 + nt*8 + lq*2;
                float v0 = acc[mt][nt][half_*2+0] + __ldg(bias + n);
                float v1 = acc[mt][nt][half_*2+1] + __ldg(bias + n + 1);
                *(float2*)&out[(size_t)row*D_MODEL + n] = make_float2(v0, v1);
            }
        }
    }
}

// ===========================================================================
// Flash attention, fp16 MMA. QTILE=128, KTILE=64, 8 warps (16 rows each).
// Q fragments from gmem (registers, loop-invariant). K [c][d], V^T [dh][c]
// staged via 3-buffer cp.async. P packs directly from S accumulators.
// KV row stride 72 halves (144B). Buffer = K(64*144) + V(64*144) = 18432B.
#define QTILE 128
#define KTILE 64
#define KV_ROW_B 144
#define KV_ROW_W 36
#define FL_BUF_BYTES 18432
#define FLASH_SMEM_BYTES (3*FL_BUF_BYTES)     // 55296

__device__ __forceinline__ void flash_issue_kv(
    uint32_t smem_u, int bufidx, int kt,
    const __half* __restrict__ kb, const __half* __restrict__ vT, int tid)
{
    uint32_t kdst = smem_u + bufidx*FL_BUF_BYTES;
    uint32_t vdst = kdst + 64*KV_ROW_B;
    #pragma unroll
    for (int i = 0; i < 2; i++) {
        int idx = tid + i*256;
        int row = idx >> 3, c8 = idx & 7;
        cp16(kdst + row*KV_ROW_B + c8*16,
             kb + ((size_t)kt*KTILE + row)*HDIM + c8*8);
    }
    #pragma unroll
    for (int i = 0; i < 2; i++) {
        int idx = tid + i*256;
        int dh = idx >> 3, c8 = idx & 7;
        cp16(vdst + dh*KV_ROW_B + c8*16,
             vT + (size_t)dh*SEQ + kt*KTILE + c8*8);
    }
}

__global__ __launch_bounds__(256,2) void flash_mma_kernel()
{
    extern __shared__ uint32_t smu[];
    uint32_t smem_u = smem_u32(smu);

    const int tid  = threadIdx.x;
    const int lane = tid & 31;
    const int wid  = tid >> 5;
    const int lq   = lane & 3;
    const int gq   = lane >> 2;

    const int qt = blockIdx.x;
    const int h  = blockIdx.y;
    const int bb = blockIdx.z;
    const int bh = bb*NHEAD + h;

    const __half* qb = g_qh + ((size_t)bh*SEQ + qt*QTILE)*HDIM;
    const __half* kb = g_kh + (size_t)bh*SEQ*HDIM;
    const __half* vT = g_vT + (size_t)bh*HDIM*SEQ;

    flash_issue_kv(smem_u, 0, 0, kb, vT, tid); CP_COMMIT();
    flash_issue_kv(smem_u, 1, 1, kb, vT, tid); CP_COMMIT();

    const int row0 = wid*16 + gq;
    const int row1 = row0 + 8;

    // Q fragments (A, m16k16 over d), loop-invariant; Q pre-scaled in gmem
    const uint32_t* qu = (const uint32_t*)qb;   // [t][d/2]
    uint32_t qa[4][4];
    #pragma unroll
    for (int kk = 0; kk < 4; kk++) {
        qa[kk][0] = qu[ row0*32 + kk*8 + lq    ];
        qa[kk][1] = qu[ row1*32 + kk*8 + lq    ];
        qa[kk][2] = qu[ row0*32 + kk*8 + lq + 4];
        qa[kk][3] = qu[ row1*32 + kk*8 + lq + 4];
    }

    float m0 = -1e30f, m1 = -1e30f, l0 = 0.f, l1 = 0.f;
    float o[8][4];
    #pragma unroll
    for (int i = 0; i < 8; i++)
        #pragma unroll
        for (int j = 0; j < 4; j++) o[i][j] = 0.f;

    for (int kt = 0; kt < SEQ/KTILE; kt++) {
        CP_WAIT(1);
        __syncthreads();
        if (kt + 2 < SEQ/KTILE) {
            flash_issue_kv(smem_u, (kt+2)%3, kt+2, kb, vT, tid);
            CP_COMMIT();
        }
        const uint32_t* Kw = smu + (kt%3)*(FL_BUF_BYTES/4);
        const uint32_t* Vw = Kw + 64*KV_ROW_W;

        // ---- S = Q K^T  (Q pre-scaled by 1/8*log2e) ----
        float s[8][4];
        #pragma unroll
        for (int nt = 0; nt < 8; nt++)
            #pragma unroll
            for (int j = 0; j < 4; j++) s[nt][j] = 0.f;

        #pragma unroll
        for (int kk = 0; kk < 4; kk++) {
            #pragma unroll
            for (int nt = 0; nt < 8; nt++) {
                uint32_t b0 = Kw[(nt*8 + gq)*KV_ROW_W + kk*8 + lq    ];
                uint32_t b1 = Kw[(nt*8 + gq)*KV_ROW_W + kk*8 + lq + 4];
                mma16(s[nt], qa[kk][0], qa[kk][1], qa[kk][2], qa[kk][3], b0, b1);
            }
        }

        // ---- online softmax (base 2) ----
        float mt0 = -1e30f, mt1 = -1e30f;
        #pragma unroll
        for (int nt = 0; nt < 8; nt++) {
            mt0 = fmaxf(mt0, fmaxf(s[nt][0], s[nt][1]));
            mt1 = fmaxf(mt1, fmaxf(s[nt][2], s[nt][3]));
        }
        mt0 = fmaxf(mt0, __shfl_xor_sync(0xffffffffu, mt0, 1));
        mt0 = fmaxf(mt0, __shfl_xor_sync(0xffffffffu, mt0, 2));
        mt1 = fmaxf(mt1, __shfl_xor_sync(0xffffffffu, mt1, 1));
        mt1 = fmaxf(mt1, __shfl_xor_sync(0xffffffffu, mt1, 2));

        float mn0 = fmaxf(m0, mt0);
        float mn1 = fmaxf(m1, mt1);
        float corr0 = exp2f(m0 - mn0);
        float corr1 = exp2f(m1 - mn1);
        m0 = mn0; m1 = mn1;

        float p[8][4];
        float sum0 = 0.f, sum1 = 0.f;
        #pragma unroll
        for (int nt = 0; nt < 8; nt++) {
            p[nt][0] = exp2f(s[nt][0] - mn0);
            p[nt][1] = exp2f(s[nt][1] - mn0);
            p[nt][2] = exp2f(s[nt][2] - mn1);
            p[nt][3] = exp2f(s[nt][3] - mn1);
            sum0 += p[nt][0] + p[nt][1];
            sum1 += p[nt][2] + p[nt][3];
        }
        sum0 += __shfl_xor_sync(0xffffffffu, sum0, 1);
        sum0 += __shfl_xor_sync(0xffffffffu, sum0, 2);
        sum1 += __shfl_xor_sync(0xffffffffu, sum1, 1);
        sum1 += __shfl_xor_sync(0xffffffffu, sum1, 2);
        l0 = l0*corr0 + sum0;
        l1 = l1*corr1 + sum1;

        #pragma unroll
        for (int nt = 0; nt < 8; nt++) {
            o[nt][0] *= corr0; o[nt][1] *= corr0;
            o[nt][2] *= corr1; o[nt][3] *= corr1;
        }

        // ---- O += P V : A fragments pack directly from P (no smem/shfl) ----
        #pragma unroll
        for (int kk = 0; kk < 4; kk++) {
            uint32_t a0 = h2pack(p[2*kk  ][0], p[2*kk  ][1]);
            uint32_t a1 = h2pack(p[2*kk  ][2], p[2*kk  ][3]);
            uint32_t a2 = h2pack(p[2*kk+1][0], p[2*kk+1][1]);
            uint32_t a3 = h2pack(p[2*kk+1][2], p[2*kk+1][3]);
            #pragma unroll
            for (int nt = 0; nt < 8; nt++) {
                uint32_t b0 = Vw[(nt*8 + gq)*KV_ROW_W + kk*8 + lq    ];
                uint32_t b1 = Vw[(nt*8 + gq)*KV_ROW_W + kk*8 + lq + 4];
                mma16(o[nt], a0, a1, a2, a3, b0, b1);
            }
        }
    }

    // epilogue: normalize, write half attn [B,T,C], C=(h, dh)
    float inv0 = 1.0f / l0;
    float inv1 = 1.0f / l1;
    #pragma unroll
    for (int nt = 0; nt < 8; nt++) {
        int d = nt*8 + lq*2;
        size_t r0g = (size_t)(bb*SEQ + qt*QTILE + row0)*D_MODEL + h*64 + d;
        size_t r1g = (size_t)(bb*SEQ + qt*QTILE + row1)*D_MODEL + h*64 + d;
        *(uint32_t*)&g_attnh[r0g] = h2pack(o[nt][0]*inv0, o[nt][1]*inv0);
        *(uint32_t*)&g_attnh[r1g] = h2pack(o[nt][2]*inv1, o[nt][3]*inv1);
    }
}

// ===========================================================================
extern "C" void kernel_launch(void* const* d_in, const int* in_sizes, int n_in,
                              void* d_out, int out_size)
{
    const float* x     = (const float*)d_in[0];
    const float* w_qkv = (const float*)d_in[1];
    const float* b_qkv = (const float*)d_in[2];
    const float* w_out = (const float*)d_in[3];
    const float* b_out = (const float*)d_in[4];
    float* out = (float*)d_out;

    (void)in_sizes; (void)n_in; (void)out_size;

    cudaFuncSetAttribute(qkv_mma_kernel,
                         cudaFuncAttributeMaxDynamicSharedMemorySize, GEMM_SMEM_BYTES);
    cudaFuncSetAttribute(out_mma_kernel,
                         cudaFuncAttributeMaxDynamicSharedMemorySize, GEMM_SMEM_BYTES);
    cudaFuncSetAttribute(flash_mma_kernel,
                         cudaFuncAttributeMaxDynamicSharedMemorySize, FLASH_SMEM_BYTES);

    __half* xh;    cudaGetSymbolAddress((void**)&xh,    g_xh);
    __half* wqkvT; cudaGetSymbolAddress((void**)&wqkvT, g_wqkvT);
    __half* woutT; cudaGetSymbolAddress((void**)&woutT, g_woutT);

    // 0) convert x to half; transpose+convert weights to half
    cvt_half_kernel<<<MTOT*D_MODEL/4/256, 256>>>(
        (const float4*)x, (uint2*)xh, MTOT*D_MODEL/4);
    {
        dim3 g1(NQKV/32, D_MODEL/32);    // w_qkv [1024][3072] -> [3072][1024]
        transcvt_half_kernel<<<g1, 256>>>(w_qkv, wqkvT, D_MODEL, NQKV);
        dim3 g2(D_MODEL/32, D_MODEL/32); // w_out [1024][1024] -> [1024][1024]
        transcvt_half_kernel<<<g2, 256>>>(w_out, woutT, D_MODEL, D_MODEL);
    }
    // 1) QKV GEMM (fp16 MMA) + bias + scatter (q scaled, v transposed)
    {
        dim3 grid(NQKV/128, MTOT/128);    // (24, 32)
        qkv_mma_kernel<<<grid, 256, GEMM_SMEM_BYTES>>>(b_qkv);
    }
    // 2) flash attention (fp16 MMA)
    {
        dim3 grid(SEQ/QTILE, NHEAD, BATCH); // (16, 16, 2)
        flash_mma_kernel<<<grid, 256, FLASH_SMEM_BYTES>>>();
    }
    // 3) out GEMM (fp16 MMA) + bias, f32 output
    {
        dim3 grid(D_MODEL/128, MTOT/128); // (8, 32)
        out_mma_kernel<<<grid, 256, GEMM_SMEM_BYTES>>>(b_out, out);
    }
}

// round 10
// speedup vs baseline: 1.9672x; 1.1051x over previous
#include <cuda_runtime.h>
#include <cuda_fp16.h>
#include <cstdint>

#define D_MODEL 1024
#define NHEAD   16
#define HDIM    64
#define BATCH   2
#define SEQ     2048
#define MTOT    (BATCH*SEQ)          // 4096
#define NQKV    (3*D_MODEL)          // 3072

// ---------------- scratch (static device globals; no allocation) ----------
__device__ __half g_qh[BATCH*NHEAD*SEQ*HDIM];    // [B,H,T,Dh]  pre-scaled
__device__ __half g_kh[BATCH*NHEAD*SEQ*HDIM];    // [B,H,T,Dh]
__device__ __half g_vT[BATCH*NHEAD*HDIM*SEQ];    // [B,H,Dh,T]  (transposed)
__device__ __half g_attnh[MTOT*D_MODEL];         // [B,T,C]
__device__ __half g_xh[MTOT*D_MODEL];            // x as half
__device__ __half g_wqkvT[NQKV*D_MODEL];         // w_qkv^T as half
__device__ __half g_woutT[D_MODEL*D_MODEL];      // w_out^T as half

// ---------------- helpers ---------------------------------------------------
__device__ __forceinline__ uint32_t smem_u32(const void* p) {
    uint32_t a;
    asm("{ .reg .u64 t; cvta.to.shared.u64 t, %1; cvt.u32.u64 %0, t; }" : "=r"(a) : "l"(p));
    return a;
}
__device__ __forceinline__ uint32_t h2pack(float lo, float hi) {
    __half2 h = __floats2half2_rn(lo, hi);
    return *(uint32_t*)&h;
}
__device__ __forceinline__ void mma16(float* c,
    uint32_t a0, uint32_t a1, uint32_t a2, uint32_t a3,
    uint32_t b0, uint32_t b1)
{
    asm volatile(
        "mma.sync.aligned.m16n8k16.row.col.f32.f16.f16.f32 "
        "{%0,%1,%2,%3}, {%4,%5,%6,%7}, {%8,%9}, {%0,%1,%2,%3};"
        : "+f"(c[0]), "+f"(c[1]), "+f"(c[2]), "+f"(c[3])
        : "r"(a0), "r"(a1), "r"(a2), "r"(a3), "r"(b0), "r"(b1));
}
__device__ __forceinline__ void ldm_x4(uint32_t* r, uint32_t addr) {
    asm volatile("ldmatrix.sync.aligned.m8n8.x4.shared.b16 {%0,%1,%2,%3}, [%4];"
        : "=r"(r[0]), "=r"(r[1]), "=r"(r[2]), "=r"(r[3]) : "r"(addr));
}
__device__ __forceinline__ void cp16(uint32_t dst, const void* src) {
    asm volatile("cp.async.cg.shared.global [%0], [%1], 16;" :: "r"(dst), "l"(src));
}
#define CP_COMMIT() asm volatile("cp.async.commit_group;" ::: "memory")
#define CP_WAIT(n)  asm volatile("cp.async.wait_group %0;" :: "n"(n) : "memory")

// ---- pre-pass: convert x to half -------------------------------------------
__global__ __launch_bounds__(256) void cvt_half_kernel(
    const float4* __restrict__ src, uint2* __restrict__ dst, int n4)
{
    int i = blockIdx.x*256 + threadIdx.x;
    if (i < n4) {
        float4 v = src[i];
        dst[i] = make_uint2(h2pack(v.x, v.y), h2pack(v.z, v.w));
    }
}
// ---- pre-pass: transpose + convert weights to half -------------------------
__global__ __launch_bounds__(256) void transcvt_half_kernel(
    const float* __restrict__ src, __half* __restrict__ dst, int R, int C)
{
    __shared__ float t[32][33];
    int bx = blockIdx.x * 32;
    int by = blockIdx.y * 32;
    int tx = threadIdx.x & 31;
    int ty = threadIdx.x >> 5;
    #pragma unroll
    for (int i = 0; i < 32; i += 8)
        t[ty + i][tx] = src[(size_t)(by + ty + i)*C + bx + tx];
    __syncthreads();
    #pragma unroll
    for (int i = 0; i < 32; i += 8)
        dst[(size_t)(bx + ty + i)*R + by + tx] = __float2half(t[tx][ty + i]);
}

// ===========================================================================
// fp16 MMA GEMM: CTA 128x128, 256 threads (8 warps, warp tile 64x32).
// K chunk 32 halves, 4-stage cp.async, ldmatrix fragments.
// smem per stage: A 128 rows x 80B + B 128 rows x 80B = 20480B.
// ===========================================================================
#define G_STAGE_BYTES 20480
#define GEMM_SMEM_BYTES (4*G_STAGE_BYTES)   // 81920

__device__ __forceinline__ void gemm_issue(
    uint32_t smem_u, int st,
    const __half* __restrict__ A, const __half* __restrict__ B,
    int m0, int n0, int k0, int tid)
{
    uint32_t sa = smem_u + st*G_STAGE_BYTES;
    uint32_t sb = sa + 128*80;
    #pragma unroll
    for (int i = 0; i < 2; i++) {
        int idx = tid + i*256;
        int row = idx >> 2, c8 = idx & 3;
        cp16(sa + row*80 + c8*16, A + (size_t)(m0+row)*D_MODEL + k0 + c8*8);
    }
    #pragma unroll
    for (int i = 0; i < 2; i++) {
        int idx = tid + i*256;
        int nb = idx >> 2, c8 = idx & 3;
        cp16(sb + nb*80 + c8*16, B + (size_t)(n0+nb)*D_MODEL + k0 + c8*8);
    }
}

__device__ __forceinline__ void gemm_tile_h(
    uint32_t smem_u,
    const __half* __restrict__ A, const __half* __restrict__ B,
    int m0, int n0, float acc[4][4][4])
{
    const int tid  = threadIdx.x;
    const int lane = tid & 31;
    const int wid  = tid >> 5;
    const int wm   = wid & 1;
    const int wn   = wid >> 1;

    // ldmatrix lane offsets (within a stage buffer)
    // A tiles ordered (r,k0),(r+8,k0),(r,k8),(r+8,k8)
    const uint32_t aOff = (uint32_t)(wm*64 + (lane & 7) + ((lane >> 3) & 1)*8)*80
                        + ((lane >> 4) & 1)*16;
    // B tiles ordered (n,k0),(n,k8),(n+8,k0),(n+8,k8)
    const uint32_t bOff = 128*80
                        + (uint32_t)(wn*32 + (lane & 7) + ((lane >> 4) & 1)*8)*80
                        + ((lane >> 3) & 1)*16;

    gemm_issue(smem_u, 0, A, B, m0, n0, 0,  tid); CP_COMMIT();
    gemm_issue(smem_u, 1, A, B, m0, n0, 32, tid); CP_COMMIT();
    gemm_issue(smem_u, 2, A, B, m0, n0, 64, tid); CP_COMMIT();

    for (int s = 0; s < 32; s++) {
        CP_WAIT(2);
        __syncthreads();
        if (s + 3 < 32) {
            gemm_issue(smem_u, (s+3)&3, A, B, m0, n0, (s+3)*32, tid);
            CP_COMMIT();
        }
        const uint32_t base = smem_u + (s&3)*G_STAGE_BYTES;

        #pragma unroll
        for (int ks = 0; ks < 2; ks++) {          // two k16 steps per chunk
            uint32_t a[4][4], b[2][4];
            #pragma unroll
            for (int mt = 0; mt < 4; mt++)
                ldm_x4(a[mt], base + aOff + mt*(16*80) + ks*32);
            #pragma unroll
            for (int np = 0; np < 2; np++)
                ldm_x4(b[np], base + bOff + np*(16*80) + ks*32);
            #pragma unroll
            for (int nt = 0; nt < 4; nt++) {
                uint32_t b0 = b[nt >> 1][(nt & 1)*2];
                uint32_t b1 = b[nt >> 1][(nt & 1)*2 + 1];
                #pragma unroll
                for (int mt = 0; mt < 4; mt++)
                    mma16(acc[mt][nt], a[mt][0], a[mt][1], a[mt][2], a[mt][3], b0, b1);
            }
        }
    }
}

// ---- GEMM 1: qkv = x @ w_qkv + b, scatter to half q(scaled)/k/vT -----------
__global__ __launch_bounds__(256,2) void qkv_mma_kernel(const float* __restrict__ bias)
{
    extern __shared__ uint32_t smg[];
    uint32_t smem_u = smem_u32(smg);

    const int n0 = blockIdx.x * 128;
    const int m0 = blockIdx.y * 128;
    const int lane = threadIdx.x & 31;
    const int wid  = threadIdx.x >> 5;
    const int wm = wid & 1, wn = wid >> 1;
    const int lq = lane & 3, gq = lane >> 2;

    float acc[4][4][4];
    #pragma unroll
    for (int i = 0; i < 4; i++)
        #pragma unroll
        for (int j = 0; j < 4; j++)
            #pragma unroll
            for (int k = 0; k < 4; k++) acc[i][j][k] = 0.f;

    gemm_tile_h(smem_u, g_xh, g_wqkvT, m0, n0, acc);

    const float QSCALE = 0.125f * 1.4426950408889634f;

    #pragma unroll
    for (int mt = 0; mt < 4; mt++) {
        int rbase = m0 + wm*64 + mt*16 + gq;
        #pragma unroll
        for (int half_ = 0; half_ < 2; half_++) {
            int row = rbase + half_*8;
            int bb = row >> 11;
            int t  = row & 2047;
            #pragma unroll
            for (int nt = 0; nt < 4; nt++) {
                int n = n0 + wn*32 + nt*8 + lq*2;
                float v0 = acc[mt][nt][half_*2+0] + __ldg(bias + n);
                float v1 = acc[mt][nt][half_*2+1] + __ldg(bias + n + 1);
                int sec = n >> 10;
                int h   = (n >> 6) & 15;
                int d   = n & 63;
                int bh  = bb*NHEAD + h;
                if (sec == 0) {
                    *(uint32_t*)&g_qh[((size_t)bh*SEQ + t)*HDIM + d] =
                        h2pack(v0*QSCALE, v1*QSCALE);
                } else if (sec == 1) {
                    *(uint32_t*)&g_kh[((size_t)bh*SEQ + t)*HDIM + d] = h2pack(v0, v1);
                } else {
                    g_vT[((size_t)bh*HDIM + d    )*SEQ + t] = __float2half(v0);
                    g_vT[((size_t)bh*HDIM + d + 1)*SEQ + t] = __float2half(v1);
                }
            }
        }
    }
}

// ---- GEMM 3: out = attn @ w_out + b (f32 output) ----------------------------
__global__ __launch_bounds__(256,2) void out_mma_kernel(
    const float* __restrict__ bias, float* __restrict__ out)
{
    extern __shared__ uint32_t smg[];
    uint32_t smem_u = smem_u32(smg);

    const int n0 = blockIdx.x * 128;
    const int m0 = blockIdx.y * 128;
    const int lane = threadIdx.x & 31;
    const int wid  = threadIdx.x >> 5;
    const int wm = wid & 1, wn = wid >> 1;
    const int lq = lane & 3, gq = lane >> 2;

    float acc[4][4][4];
    #pragma unroll
    for (int i = 0; i < 4; i++)
        #pragma unroll
        for (int j = 0; j < 4; j++)
            #pragma unroll
            for (int k = 0; k < 4; k++) acc[i][j][k] = 0.f;

    gemm_tile_h(smem_u, g_attnh, g_woutT, m0, n0, acc);

    #pragma unroll
    for (int mt = 0; mt < 4; mt++) {
        int rbase = m0 + wm*64 + mt*16 + gq;
        #pragma unroll
        for (int half_ = 0; half_ < 2; half_++) {
            int row = rbase + half_*8;
            #pragma unroll
            for (int nt = 0; nt < 4; nt++) {
                int n = n0 + wn*32 + nt*8 + lq*2;
                float v0 = acc[mt][nt][half_*2+0] + __ldg(bias + n);
                float v1 = acc[mt][nt][half_*2+1] + __ldg(bias + n + 1);
                *(float2*)&out[(size_t)row*D_MODEL + n] = make_float2(v0, v1);
            }
        }
    }
}

// ===========================================================================
// Flash attention, fp16 MMA + ldmatrix. QTILE=128, KTILE=64, 8 warps.
// K [c][d], V^T [dh][c] in 3-buffer cp.async; P packs from S accumulators.
// KV row stride 144B (conflict-free for ldmatrix: banks 4i).
#define QTILE 128
#define KTILE 64
#define KV_ROW_B 144
#define FL_BUF_BYTES 18432
#define FLASH_SMEM_BYTES (3*FL_BUF_BYTES)     // 55296

__device__ __forceinline__ void flash_issue_kv(
    uint32_t smem_u, int bufidx, int kt,
    const __half* __restrict__ kb, const __half* __restrict__ vT, int tid)
{
    uint32_t kdst = smem_u + bufidx*FL_BUF_BYTES;
    uint32_t vdst = kdst + 64*KV_ROW_B;
    #pragma unroll
    for (int i = 0; i < 2; i++) {
        int idx = tid + i*256;
        int row = idx >> 3, c8 = idx & 7;
        cp16(kdst + row*KV_ROW_B + c8*16,
             kb + ((size_t)kt*KTILE + row)*HDIM + c8*8);
    }
    #pragma unroll
    for (int i = 0; i < 2; i++) {
        int idx = tid + i*256;
        int dh = idx >> 3, c8 = idx & 7;
        cp16(vdst + dh*KV_ROW_B + c8*16,
             vT + (size_t)dh*SEQ + kt*KTILE + c8*8);
    }
}

__global__ __launch_bounds__(256,2) void flash_mma_kernel()
{
    extern __shared__ uint32_t smu[];
    uint32_t smem_u = smem_u32(smu);

    const int tid  = threadIdx.x;
    const int lane = tid & 31;
    const int wid  = tid >> 5;
    const int lq   = lane & 3;
    const int gq   = lane >> 2;

    const int qt = blockIdx.x;
    const int h  = blockIdx.y;
    const int bb = blockIdx.z;
    const int bh = bb*NHEAD + h;

    const __half* qb = g_qh + ((size_t)bh*SEQ + qt*QTILE)*HDIM;
    const __half* kb = g_kh + (size_t)bh*SEQ*HDIM;
    const __half* vT = g_vT + (size_t)bh*HDIM*SEQ;

    flash_issue_kv(smem_u, 0, 0, kb, vT, tid); CP_COMMIT();
    flash_issue_kv(smem_u, 1, 1, kb, vT, tid); CP_COMMIT();

    const int row0 = wid*16 + gq;
    const int row1 = row0 + 8;

    // B-fragment ldmatrix lane offset (rows = K's c, or V's dh; stride 144B)
    // tiles ordered (n,k0),(n,k8),(n+8,k0),(n+8,k8)
    const uint32_t bOff = (uint32_t)((lane & 7) + ((lane >> 4) & 1)*8)*KV_ROW_B
                        + ((lane >> 3) & 1)*16;

    // Q fragments (loop-invariant, pre-scaled in gmem)
    const uint32_t* qu = (const uint32_t*)qb;
    uint32_t qa[4][4];
    #pragma unroll
    for (int kk = 0; kk < 4; kk++) {
        qa[kk][0] = qu[ row0*32 + kk*8 + lq    ];
        qa[kk][1] = qu[ row1*32 + kk*8 + lq    ];
        qa[kk][2] = qu[ row0*32 + kk*8 + lq + 4];
        qa[kk][3] = qu[ row1*32 + kk*8 + lq + 4];
    }

    float m0 = -1e30f, m1 = -1e30f, l0 = 0.f, l1 = 0.f;
    float o[8][4];
    #pragma unroll
    for (int i = 0; i < 8; i++)
        #pragma unroll
        for (int j = 0; j < 4; j++) o[i][j] = 0.f;

    for (int kt = 0; kt < SEQ/KTILE; kt++) {
        CP_WAIT(1);
        __syncthreads();
        if (kt + 2 < SEQ/KTILE) {
            flash_issue_kv(smem_u, (kt+2)%3, kt+2, kb, vT, tid);
            CP_COMMIT();
        }
        const uint32_t kBase = smem_u + (kt%3)*FL_BUF_BYTES;
        const uint32_t vBase = kBase + 64*KV_ROW_B;

        // ---- S = Q K^T ----
        float s[8][4];
        #pragma unroll
        for (int nt = 0; nt < 8; nt++)
            #pragma unroll
            for (int j = 0; j < 4; j++) s[nt][j] = 0.f;

        #pragma unroll
        for (int kk = 0; kk < 4; kk++) {
            uint32_t b[4][4];
            #pragma unroll
            for (int np = 0; np < 4; np++)
                ldm_x4(b[np], kBase + bOff + np*(16*KV_ROW_B) + kk*32);
            #pragma unroll
            for (int nt = 0; nt < 8; nt++) {
                uint32_t b0 = b[nt >> 1][(nt & 1)*2];
                uint32_t b1 = b[nt >> 1][(nt & 1)*2 + 1];
                mma16(s[nt], qa[kk][0], qa[kk][1], qa[kk][2], qa[kk][3], b0, b1);
            }
        }

        // ---- online softmax (base 2) ----
        float mt0 = -1e30f, mt1 = -1e30f;
        #pragma unroll
        for (int nt = 0; nt < 8; nt++) {
            mt0 = fmaxf(mt0, fmaxf(s[nt][0], s[nt][1]));
            mt1 = fmaxf(mt1, fmaxf(s[nt][2], s[nt][3]));
        }
        mt0 = fmaxf(mt0, __shfl_xor_sync(0xffffffffu, mt0, 1));
        mt0 = fmaxf(mt0, __shfl_xor_sync(0xffffffffu, mt0, 2));
        mt1 = fmaxf(mt1, __shfl_xor_sync(0xffffffffu, mt1, 1));
        mt1 = fmaxf(mt1, __shfl_xor_sync(0xffffffffu, mt1, 2));

        float mn0 = fmaxf(m0, mt0);
        float mn1 = fmaxf(m1, mt1);
        float corr0 = exp2f(m0 - mn0);
        float corr1 = exp2f(m1 - mn1);
        m0 = mn0; m1 = mn1;

        float p[8][4];
        float sum0 = 0.f, sum1 = 0.f;
        #pragma unroll
        for (int nt = 0; nt < 8; nt++) {
            p[nt][0] = exp2f(s[nt][0] - mn0);
            p[nt][1] = exp2f(s[nt][1] - mn0);
            p[nt][2] = exp2f(s[nt][2] - mn1);
            p[nt][3] = exp2f(s[nt][3] - mn1);
            sum0 += p[nt][0] + p[nt][1];
            sum1 += p[nt][2] + p[nt][3];
        }
        sum0 += __shfl_xor_sync(0xffffffffu, sum0, 1);
        sum0 += __shfl_xor_sync(0xffffffffu, sum0, 2);
        sum1 += __shfl_xor_sync(0xffffffffu, sum1, 1);
        sum1 += __shfl_xor_sync(0xffffffffu, sum1, 2);
        l0 = l0*corr0 + sum0;
        l1 = l1*corr1 + sum1;

        #pragma unroll
        for (int nt = 0; nt < 8; nt++) {
            o[nt][0] *= corr0; o[nt][1] *= corr0;
            o[nt][2] *= corr1; o[nt][3] *= corr1;
        }

        // ---- O += P V ----
        #pragma unroll
        for (int kk = 0; kk < 4; kk++) {
            uint32_t a0 = h2pack(p[2*kk  ][0], p[2*kk  ][1]);
            uint32_t a1 = h2pack(p[2*kk  ][2], p[2*kk  ][3]);
            uint32_t a2 = h2pack(p[2*kk+1][0], p[2*kk+1][1]);
            uint32_t a3 = h2pack(p[2*kk+1][2], p[2*kk+1][3]);
            uint32_t b[4][4];
            #pragma unroll
            for (int np = 0; np < 4; np++)
                ldm_x4(b[np], vBase + bOff + np*(16*KV_ROW_B) + kk*32);
            #pragma unroll
            for (int nt = 0; nt < 8; nt++) {
                uint32_t b0 = b[nt >> 1][(nt & 1)*2];
                uint32_t b1 = b[nt >> 1][(nt & 1)*2 + 1];
                mma16(o[nt], a0, a1, a2, a3, b0, b1);
            }
        }
    }

    float inv0 = 1.0f / l0;
    float inv1 = 1.0f / l1;
    #pragma unroll
    for (int nt = 0; nt < 8; nt++) {
        int d = nt*8 + lq*2;
        size_t r0g = (size_t)(bb*SEQ + qt*QTILE + row0)*D_MODEL + h*64 + d;
        size_t r1g = (size_t)(bb*SEQ + qt*QTILE + row1)*D_MODEL + h*64 + d;
        *(uint32_t*)&g_attnh[r0g] = h2pack(o[nt][0]*inv0, o[nt][1]*inv0);
        *(uint32_t*)&g_attnh[r1g] = h2pack(o[nt][2]*inv1, o[nt][3]*inv1);
    }
}

// ===========================================================================
extern "C" void kernel_launch(void* const* d_in, const int* in_sizes, int n_in,
                              void* d_out, int out_size)
{
    const float* x     = (const float*)d_in[0];
    const float* w_qkv = (const float*)d_in[1];
    const float* b_qkv = (const float*)d_in[2];
    const float* w_out = (const float*)d_in[3];
    const float* b_out = (const float*)d_in[4];
    float* out = (float*)d_out;

    (void)in_sizes; (void)n_in; (void)out_size;

    cudaFuncSetAttribute(qkv_mma_kernel,
                         cudaFuncAttributeMaxDynamicSharedMemorySize, GEMM_SMEM_BYTES);
    cudaFuncSetAttribute(out_mma_kernel,
                         cudaFuncAttributeMaxDynamicSharedMemorySize, GEMM_SMEM_BYTES);
    cudaFuncSetAttribute(flash_mma_kernel,
                         cudaFuncAttributeMaxDynamicSharedMemorySize, FLASH_SMEM_BYTES);

    __half* xh;    cudaGetSymbolAddress((void**)&xh,    g_xh);
    __half* wqkvT; cudaGetSymbolAddress((void**)&wqkvT, g_wqkvT);
    __half* woutT; cudaGetSymbolAddress((void**)&woutT, g_woutT);

    // 0) convert x to half; transpose+convert weights to half
    cvt_half_kernel<<<MTOT*D_MODEL/4/256, 256>>>(
        (const float4*)x, (uint2*)xh, MTOT*D_MODEL/4);
    {
        dim3 g1(NQKV/32, D_MODEL/32);
        transcvt_half_kernel<<<g1, 256>>>(w_qkv, wqkvT, D_MODEL, NQKV);
        dim3 g2(D_MODEL/32, D_MODEL/32);
        transcvt_half_kernel<<<g2, 256>>>(w_out, woutT, D_MODEL, D_MODEL);
    }
    // 1) QKV GEMM (fp16 MMA + ldmatrix)
    {
        dim3 grid(NQKV/128, MTOT/128);
        qkv_mma_kernel<<<grid, 256, GEMM_SMEM_BYTES>>>(b_qkv);
    }
    // 2) flash attention (fp16 MMA + ldmatrix)
    {
        dim3 grid(SEQ/QTILE, NHEAD, BATCH);
        flash_mma_kernel<<<grid, 256, FLASH_SMEM_BYTES>>>();
    }
    // 3) out GEMM (fp16 MMA + ldmatrix)
    {
        dim3 grid(D_MODEL/128, MTOT/128);
        out_mma_kernel<<<grid, 256, GEMM_SMEM_BYTES>>>(b_out, out);
    }
}

// round 11
// speedup vs baseline: 2.0410x; 1.0375x over previous
#include <cuda_runtime.h>
#include <cuda_fp16.h>
#include <cstdint>

#define D_MODEL 1024
#define NHEAD   16
#define HDIM    64
#define BATCH   2
#define SEQ     2048
#define MTOT    (BATCH*SEQ)          // 4096
#define NQKV    (3*D_MODEL)          // 3072

// ---------------- scratch (static device globals; no allocation) ----------
__device__ __half g_qh[BATCH*NHEAD*SEQ*HDIM];    // [B,H,T,Dh]  pre-scaled
__device__ __half g_kh[BATCH*NHEAD*SEQ*HDIM];    // [B,H,T,Dh]
__device__ __half g_vT[BATCH*NHEAD*HDIM*SEQ];    // [B,H,Dh,T]  (transposed)
__device__ __half g_attnh[MTOT*D_MODEL];         // [B,T,C]
__device__ __half g_xh[MTOT*D_MODEL];            // x as half
__device__ __half g_wqkvT[NQKV*D_MODEL];         // w_qkv^T as half
__device__ __half g_woutT[D_MODEL*D_MODEL];      // w_out^T as half

// ---------------- helpers ---------------------------------------------------
__device__ __forceinline__ uint32_t smem_u32(const void* p) {
    uint32_t a;
    asm("{ .reg .u64 t; cvta.to.shared.u64 t, %1; cvt.u32.u64 %0, t; }" : "=r"(a) : "l"(p));
    return a;
}
__device__ __forceinline__ uint32_t h2pack(float lo, float hi) {
    __half2 h = __floats2half2_rn(lo, hi);
    return *(uint32_t*)&h;
}
__device__ __forceinline__ void mma16(float* c,
    uint32_t a0, uint32_t a1, uint32_t a2, uint32_t a3,
    uint32_t b0, uint32_t b1)
{
    asm volatile(
        "mma.sync.aligned.m16n8k16.row.col.f32.f16.f16.f32 "
        "{%0,%1,%2,%3}, {%4,%5,%6,%7}, {%8,%9}, {%0,%1,%2,%3};"
        : "+f"(c[0]), "+f"(c[1]), "+f"(c[2]), "+f"(c[3])
        : "r"(a0), "r"(a1), "r"(a2), "r"(a3), "r"(b0), "r"(b1));
}
__device__ __forceinline__ void ldm_x4(uint32_t* r, uint32_t addr) {
    asm volatile("ldmatrix.sync.aligned.m8n8.x4.shared.b16 {%0,%1,%2,%3}, [%4];"
        : "=r"(r[0]), "=r"(r[1]), "=r"(r[2]), "=r"(r[3]) : "r"(addr));
}
__device__ __forceinline__ void cp16(uint32_t dst, const void* src) {
    asm volatile("cp.async.cg.shared.global [%0], [%1], 16;" :: "r"(dst), "l"(src));
}
#define CP_COMMIT() asm volatile("cp.async.commit_group;" ::: "memory")
#define CP_WAIT(n)  asm volatile("cp.async.wait_group %0;" :: "n"(n) : "memory")

// ---- pre-pass: convert x to half -------------------------------------------
__global__ __launch_bounds__(256) void cvt_half_kernel(
    const float4* __restrict__ src, uint2* __restrict__ dst, int n4)
{
    int i = blockIdx.x*256 + threadIdx.x;
    if (i < n4) {
        float4 v = src[i];
        dst[i] = make_uint2(h2pack(v.x, v.y), h2pack(v.z, v.w));
    }
}
// ---- pre-pass: transpose + convert weights to half -------------------------
__global__ __launch_bounds__(256) void transcvt_half_kernel(
    const float* __restrict__ src, __half* __restrict__ dst, int R, int C)
{
    __shared__ float t[32][33];
    int bx = blockIdx.x * 32;
    int by = blockIdx.y * 32;
    int tx = threadIdx.x & 31;
    int ty = threadIdx.x >> 5;
    #pragma unroll
    for (int i = 0; i < 32; i += 8)
        t[ty + i][tx] = src[(size_t)(by + ty + i)*C + bx + tx];
    __syncthreads();
    #pragma unroll
    for (int i = 0; i < 32; i += 8)
        dst[(size_t)(bx + ty + i)*R + by + tx] = __float2half(t[tx][ty + i]);
}

// ===========================================================================
// fp16 MMA GEMM: CTA 128x128, 256 threads (8 warps, warp tile 64x32).
// K chunk 64 halves, 3-stage cp.async, ldmatrix fragments.
// Stage: A 128 rows x 144B + B 128 rows x 144B = 36864B; 3 stages = 110592B.
// Row = 128B data + 16B pad (conflict-free ldmatrix: banks 36i mod 32).
// ===========================================================================
#define G_ROW_B 144
#define G_STAGE_BYTES 36864
#define GEMM_SMEM_BYTES (3*G_STAGE_BYTES)   // 110592
#define NCHUNKS (D_MODEL/64)                // 16

__device__ __forceinline__ void gemm_issue(
    uint32_t smem_u, int st,
    const __half* __restrict__ A, const __half* __restrict__ B,
    int m0, int n0, int k0, int tid)
{
    uint32_t sa = smem_u + st*G_STAGE_BYTES;
    uint32_t sb = sa + 128*G_ROW_B;
    const int row = tid >> 3;          // 0..31 (+32*i)
    const int c8  = tid & 7;           // 0..7
    #pragma unroll
    for (int i = 0; i < 4; i++) {
        int r = i*32 + row;
        cp16(sa + r*G_ROW_B + c8*16, A + (size_t)(m0+r)*D_MODEL + k0 + c8*8);
    }
    #pragma unroll
    for (int i = 0; i < 4; i++) {
        int r = i*32 + row;
        cp16(sb + r*G_ROW_B + c8*16, B + (size_t)(n0+r)*D_MODEL + k0 + c8*8);
    }
}

__device__ __forceinline__ void gemm_tile_h(
    uint32_t smem_u,
    const __half* __restrict__ A, const __half* __restrict__ B,
    int m0, int n0, float acc[4][4][4])
{
    const int tid  = threadIdx.x;
    const int lane = tid & 31;
    const int wid  = tid >> 5;
    const int wm   = wid & 1;
    const int wn   = wid >> 1;

    // ldmatrix lane offsets (within a stage buffer)
    // A tiles ordered (r,k0),(r+8,k0),(r,k8),(r+8,k8)
    const uint32_t aOff = (uint32_t)(wm*64 + (lane & 7) + ((lane >> 3) & 1)*8)*G_ROW_B
                        + ((lane >> 4) & 1)*16;
    // B tiles ordered (n,k0),(n,k8),(n+8,k0),(n+8,k8)
    const uint32_t bOff = 128*G_ROW_B
                        + (uint32_t)(wn*32 + (lane & 7) + ((lane >> 4) & 1)*8)*G_ROW_B
                        + ((lane >> 3) & 1)*16;

    gemm_issue(smem_u, 0, A, B, m0, n0, 0,  tid); CP_COMMIT();
    gemm_issue(smem_u, 1, A, B, m0, n0, 64, tid); CP_COMMIT();

    for (int s = 0; s < NCHUNKS; s++) {
        CP_WAIT(1);
        __syncthreads();
        if (s + 2 < NCHUNKS) {
            int st = (s+2)%3;
            gemm_issue(smem_u, st, A, B, m0, n0, (s+2)*64, tid);
            CP_COMMIT();
        }
        const uint32_t base = smem_u + (s%3)*G_STAGE_BYTES;

        #pragma unroll
        for (int ks = 0; ks < 4; ks++) {          // four k16 steps per chunk
            uint32_t a[4][4], b[2][4];
            #pragma unroll
            for (int mt = 0; mt < 4; mt++)
                ldm_x4(a[mt], base + aOff + mt*(16*G_ROW_B) + ks*32);
            #pragma unroll
            for (int np = 0; np < 2; np++)
                ldm_x4(b[np], base + bOff + np*(16*G_ROW_B) + ks*32);
            #pragma unroll
            for (int nt = 0; nt < 4; nt++) {
                uint32_t b0 = b[nt >> 1][(nt & 1)*2];
                uint32_t b1 = b[nt >> 1][(nt & 1)*2 + 1];
                #pragma unroll
                for (int mt = 0; mt < 4; mt++)
                    mma16(acc[mt][nt], a[mt][0], a[mt][1], a[mt][2], a[mt][3], b0, b1);
            }
        }
        __syncthreads();   // all warps done reading stage s before it is refilled
    }
}

// ---- GEMM 1: qkv = x @ w_qkv + b, scatter to half q(scaled)/k/vT -----------
__global__ __launch_bounds__(256,2) void qkv_mma_kernel(const float* __restrict__ bias)
{
    extern __shared__ uint32_t smg[];
    uint32_t smem_u = smem_u32(smg);

    const int n0 = blockIdx.x * 128;
    const int m0 = blockIdx.y * 128;
    const int lane = threadIdx.x & 31;
    const int wid  = threadIdx.x >> 5;
    const int wm = wid & 1, wn = wid >> 1;
    const int lq = lane & 3, gq = lane >> 2;

    float acc[4][4][4];
    #pragma unroll
    for (int i = 0; i < 4; i++)
        #pragma unroll
        for (int j = 0; j < 4; j++)
            #pragma unroll
            for (int k = 0; k < 4; k++) acc[i][j][k] = 0.f;

    gemm_tile_h(smem_u, g_xh, g_wqkvT, m0, n0, acc);

    const float QSCALE = 0.125f * 1.4426950408889634f;

    #pragma unroll
    for (int mt = 0; mt < 4; mt++) {
        int rbase = m0 + wm*64 + mt*16 + gq;
        #pragma unroll
        for (int half_ = 0; half_ < 2; half_++) {
            int row = rbase + half_*8;
            int bb = row >> 11;
            int t  = row & 2047;
            #pragma unroll
            for (int nt = 0; nt < 4; nt++) {
                int n = n0 + wn*32 + nt*8 + lq*2;
                float v0 = acc[mt][nt][half_*2+0] + __ldg(bias + n);
                float v1 = acc[mt][nt][half_*2+1] + __ldg(bias + n + 1);
                int sec = n >> 10;
                int h   = (n >> 6) & 15;
                int d   = n & 63;
                int bh  = bb*NHEAD + h;
                if (sec == 0) {
                    *(uint32_t*)&g_qh[((size_t)bh*SEQ + t)*HDIM + d] =
                        h2pack(v0*QSCALE, v1*QSCALE);
                } else if (sec == 1) {
                    *(uint32_t*)&g_kh[((size_t)bh*SEQ + t)*HDIM + d] = h2pack(v0, v1);
                } else {
                    g_vT[((size_t)bh*HDIM + d    )*SEQ + t] = __float2half(v0);
                    g_vT[((size_t)bh*HDIM + d + 1)*SEQ + t] = __float2half(v1);
                }
            }
        }
    }
}

// ---- GEMM 3: out = attn @ w_out + b (f32 output) ----------------------------
__global__ __launch_bounds__(256,2) void out_mma_kernel(
    const float* __restrict__ bias, float* __restrict__ out)
{
    extern __shared__ uint32_t smg[];
    uint32_t smem_u = smem_u32(smg);

    const int n0 = blockIdx.x * 128;
    const int m0 = blockIdx.y * 128;
    const int lane = threadIdx.x & 31;
    const int wid  = threadIdx.x >> 5;
    const int wm = wid & 1, wn = wid >> 1;
    const int lq = lane & 3, gq = lane >> 2;

    float acc[4][4][4];
    #pragma unroll
    for (int i = 0; i < 4; i++)
        #pragma unroll
        for (int j = 0; j < 4; j++)
            #pragma unroll
            for (int k = 0; k < 4; k++) acc[i][j][k] = 0.f;

    gemm_tile_h(smem_u, g_attnh, g_woutT, m0, n0, acc);

    #pragma unroll
    for (int mt = 0; mt < 4; mt++) {
        int rbase = m0 + wm*64 + mt*16 + gq;
        #pragma unroll
        for (int half_ = 0; half_ < 2; half_++) {
            int row = rbase + half_*8;
            #pragma unroll
            for (int nt = 0; nt < 4; nt++) {
                int n = n0 + wn*32 + nt*8 + lq*2;
                float v0 = acc[mt][nt][half_*2+0] + __ldg(bias + n);
                float v1 = acc[mt][nt][half_*2+1] + __ldg(bias + n + 1);
                *(float2*)&out[(size_t)row*D_MODEL + n] = make_float2(v0, v1);
            }
        }
    }
}

// ===========================================================================
// Flash attention, fp16 MMA + ldmatrix (unchanged from R10 — at ~95% of the
// legacy-HMMA ceiling). QTILE=128, KTILE=64, 8 warps.
#define QTILE 128
#define KTILE 64
#define KV_ROW_B 144
#define FL_BUF_BYTES 18432
#define FLASH_SMEM_BYTES (3*FL_BUF_BYTES)     // 55296

__device__ __forceinline__ void flash_issue_kv(
    uint32_t smem_u, int bufidx, int kt,
    const __half* __restrict__ kb, const __half* __restrict__ vT, int tid)
{
    uint32_t kdst = smem_u + bufidx*FL_BUF_BYTES;
    uint32_t vdst = kdst + 64*KV_ROW_B;
    #pragma unroll
    for (int i = 0; i < 2; i++) {
        int idx = tid + i*256;
        int row = idx >> 3, c8 = idx & 7;
        cp16(kdst + row*KV_ROW_B + c8*16,
             kb + ((size_t)kt*KTILE + row)*HDIM + c8*8);
    }
    #pragma unroll
    for (int i = 0; i < 2; i++) {
        int idx = tid + i*256;
        int dh = idx >> 3, c8 = idx & 7;
        cp16(vdst + dh*KV_ROW_B + c8*16,
             vT + (size_t)dh*SEQ + kt*KTILE + c8*8);
    }
}

__global__ __launch_bounds__(256,2) void flash_mma_kernel()
{
    extern __shared__ uint32_t smu[];
    uint32_t smem_u = smem_u32(smu);

    const int tid  = threadIdx.x;
    const int lane = tid & 31;
    const int wid  = tid >> 5;
    const int lq   = lane & 3;
    const int gq   = lane >> 2;

    const int qt = blockIdx.x;
    const int h  = blockIdx.y;
    const int bb = blockIdx.z;
    const int bh = bb*NHEAD + h;

    const __half* qb = g_qh + ((size_t)bh*SEQ + qt*QTILE)*HDIM;
    const __half* kb = g_kh + (size_t)bh*SEQ*HDIM;
    const __half* vT = g_vT + (size_t)bh*HDIM*SEQ;

    flash_issue_kv(smem_u, 0, 0, kb, vT, tid); CP_COMMIT();
    flash_issue_kv(smem_u, 1, 1, kb, vT, tid); CP_COMMIT();

    const int row0 = wid*16 + gq;
    const int row1 = row0 + 8;

    const uint32_t bOff = (uint32_t)((lane & 7) + ((lane >> 4) & 1)*8)*KV_ROW_B
                        + ((lane >> 3) & 1)*16;

    const uint32_t* qu = (const uint32_t*)qb;
    uint32_t qa[4][4];
    #pragma unroll
    for (int kk = 0; kk < 4; kk++) {
        qa[kk][0] = qu[ row0*32 + kk*8 + lq    ];
        qa[kk][1] = qu[ row1*32 + kk*8 + lq    ];
        qa[kk][2] = qu[ row0*32 + kk*8 + lq + 4];
        qa[kk][3] = qu[ row1*32 + kk*8 + lq + 4];
    }

    float m0 = -1e30f, m1 = -1e30f, l0 = 0.f, l1 = 0.f;
    float o[8][4];
    #pragma unroll
    for (int i = 0; i < 8; i++)
        #pragma unroll
        for (int j = 0; j < 4; j++) o[i][j] = 0.f;

    for (int kt = 0; kt < SEQ/KTILE; kt++) {
        CP_WAIT(1);
        __syncthreads();
        if (kt + 2 < SEQ/KTILE) {
            flash_issue_kv(smem_u, (kt+2)%3, kt+2, kb, vT, tid);
            CP_COMMIT();
        }
        const uint32_t kBase = smem_u + (kt%3)*FL_BUF_BYTES;
        const uint32_t vBase = kBase + 64*KV_ROW_B;

        float s[8][4];
        #pragma unroll
        for (int nt = 0; nt < 8; nt++)
            #pragma unroll
            for (int j = 0; j < 4; j++) s[nt][j] = 0.f;

        #pragma unroll
        for (int kk = 0; kk < 4; kk++) {
            uint32_t b[4][4];
            #pragma unroll
            for (int np = 0; np < 4; np++)
                ldm_x4(b[np], kBase + bOff + np*(16*KV_ROW_B) + kk*32);
            #pragma unroll
            for (int nt = 0; nt < 8; nt++) {
                uint32_t b0 = b[nt >> 1][(nt & 1)*2];
                uint32_t b1 = b[nt >> 1][(nt & 1)*2 + 1];
                mma16(s[nt], qa[kk][0], qa[kk][1], qa[kk][2], qa[kk][3], b0, b1);
            }
        }

        float mt0 = -1e30f, mt1 = -1e30f;
        #pragma unroll
        for (int nt = 0; nt < 8; nt++) {
            mt0 = fmaxf(mt0, fmaxf(s[nt][0], s[nt][1]));
            mt1 = fmaxf(mt1, fmaxf(s[nt][2], s[nt][3]));
        }
        mt0 = fmaxf(mt0, __shfl_xor_sync(0xffffffffu, mt0, 1));
        mt0 = fmaxf(mt0, __shfl_xor_sync(0xffffffffu, mt0, 2));
        mt1 = fmaxf(mt1, __shfl_xor_sync(0xffffffffu, mt1, 1));
        mt1 = fmaxf(mt1, __shfl_xor_sync(0xffffffffu, mt1, 2));

        float mn0 = fmaxf(m0, mt0);
        float mn1 = fmaxf(m1, mt1);
        float corr0 = exp2f(m0 - mn0);
        float corr1 = exp2f(m1 - mn1);
        m0 = mn0; m1 = mn1;

        float p[8][4];
        float sum0 = 0.f, sum1 = 0.f;
        #pragma unroll
        for (int nt = 0; nt < 8; nt++) {
            p[nt][0] = exp2f(s[nt][0] - mn0);
            p[nt][1] = exp2f(s[nt][1] - mn0);
            p[nt][2] = exp2f(s[nt][2] - mn1);
            p[nt][3] = exp2f(s[nt][3] - mn1);
            sum0 += p[nt][0] + p[nt][1];
            sum1 += p[nt][2] + p[nt][3];
        }
        sum0 += __shfl_xor_sync(0xffffffffu, sum0, 1);
        sum0 += __shfl_xor_sync(0xffffffffu, sum0, 2);
        sum1 += __shfl_xor_sync(0xffffffffu, sum1, 1);
        sum1 += __shfl_xor_sync(0xffffffffu, sum1, 2);
        l0 = l0*corr0 + sum0;
        l1 = l1*corr1 + sum1;

        #pragma unroll
        for (int nt = 0; nt < 8; nt++) {
            o[nt][0] *= corr0; o[nt][1] *= corr0;
            o[nt][2] *= corr1; o[nt][3] *= corr1;
        }

        #pragma unroll
        for (int kk = 0; kk < 4; kk++) {
            uint32_t a0 = h2pack(p[2*kk  ][0], p[2*kk  ][1]);
            uint32_t a1 = h2pack(p[2*kk  ][2], p[2*kk  ][3]);
            uint32_t a2 = h2pack(p[2*kk+1][0], p[2*kk+1][1]);
            uint32_t a3 = h2pack(p[2*kk+1][2], p[2*kk+1][3]);
            uint32_t b[4][4];
            #pragma unroll
            for (int np = 0; np < 4; np++)
                ldm_x4(b[np], vBase + bOff + np*(16*KV_ROW_B) + kk*32);
            #pragma unroll
            for (int nt = 0; nt < 8; nt++) {
                uint32_t b0 = b[nt >> 1][(nt & 1)*2];
                uint32_t b1 = b[nt >> 1][(nt & 1)*2 + 1];
                mma16(o[nt], a0, a1, a2, a3, b0, b1);
            }
        }
    }

    float inv0 = 1.0f / l0;
    float inv1 = 1.0f / l1;
    #pragma unroll
    for (int nt = 0; nt < 8; nt++) {
        int d = nt*8 + lq*2;
        size_t r0g = (size_t)(bb*SEQ + qt*QTILE + row0)*D_MODEL + h*64 + d;
        size_t r1g = (size_t)(bb*SEQ + qt*QTILE + row1)*D_MODEL + h*64 + d;
        *(uint32_t*)&g_attnh[r0g] = h2pack(o[nt][0]*inv0, o[nt][1]*inv0);
        *(uint32_t*)&g_attnh[r1g] = h2pack(o[nt][2]*inv1, o[nt][3]*inv1);
    }
}

// ===========================================================================
extern "C" void kernel_launch(void* const* d_in, const int* in_sizes, int n_in,
                              void* d_out, int out_size)
{
    const float* x     = (const float*)d_in[0];
    const float* w_qkv = (const float*)d_in[1];
    const float* b_qkv = (const float*)d_in[2];
    const float* w_out = (const float*)d_in[3];
    const float* b_out = (const float*)d_in[4];
    float* out = (float*)d_out;

    (void)in_sizes; (void)n_in; (void)out_size;

    cudaFuncSetAttribute(qkv_mma_kernel,
                         cudaFuncAttributeMaxDynamicSharedMemorySize, GEMM_SMEM_BYTES);
    cudaFuncSetAttribute(out_mma_kernel,
                         cudaFuncAttributeMaxDynamicSharedMemorySize, GEMM_SMEM_BYTES);
    cudaFuncSetAttribute(flash_mma_kernel,
                         cudaFuncAttributeMaxDynamicSharedMemorySize, FLASH_SMEM_BYTES);

    __half* xh;    cudaGetSymbolAddress((void**)&xh,    g_xh);
    __half* wqkvT; cudaGetSymbolAddress((void**)&wqkvT, g_wqkvT);
    __half* woutT; cudaGetSymbolAddress((void**)&woutT, g_woutT);

    // 0) convert x to half; transpose+convert weights to half
    cvt_half_kernel<<<MTOT*D_MODEL/4/256, 256>>>(
        (const float4*)x, (uint2*)xh, MTOT*D_MODEL/4);
    {
        dim3 g1(NQKV/32, D_MODEL/32);
        transcvt_half_kernel<<<g1, 256>>>(w_qkv, wqkvT, D_MODEL, NQKV);
        dim3 g2(D_MODEL/32, D_MODEL/32);
        transcvt_half_kernel<<<g2, 256>>>(w_out, woutT, D_MODEL, D_MODEL);
    }
    // 1) QKV GEMM (fp16 MMA + ldmatrix, k64 3-stage)
    {
        dim3 grid(NQKV/128, MTOT/128);
        qkv_mma_kernel<<<grid, 256, GEMM_SMEM_BYTES>>>(b_qkv);
    }
    // 2) flash attention (fp16 MMA + ldmatrix)
    {
        dim3 grid(SEQ/QTILE, NHEAD, BATCH);
        flash_mma_kernel<<<grid, 256, FLASH_SMEM_BYTES>>>();
    }
    // 3) out GEMM (fp16 MMA + ldmatrix, k64 3-stage)
    {
        dim3 grid(D_MODEL/128, MTOT/128);
        out_mma_kernel<<<grid, 256, GEMM_SMEM_BYTES>>>(b_out, out);
    }
}

// round 12
// speedup vs baseline: 2.1055x; 1.0316x over previous
#include <cuda_runtime.h>
#include <cuda_fp16.h>
#include <cstdint>

#define D_MODEL 1024
#define NHEAD   16
#define HDIM    64
#define BATCH   2
#define SEQ     2048
#define MTOT    (BATCH*SEQ)          // 4096
#define NQKV    (3*D_MODEL)          // 3072

// ---------------- scratch (static device globals; no allocation) ----------
__device__ __half g_qh[BATCH*NHEAD*SEQ*HDIM];    // [B,H,T,Dh]  pre-scaled
__device__ __half g_kh[BATCH*NHEAD*SEQ*HDIM];    // [B,H,T,Dh]
__device__ __half g_vT[BATCH*NHEAD*HDIM*SEQ];    // [B,H,Dh,T]  (transposed)
__device__ __half g_attnh[MTOT*D_MODEL];         // [B,T,C]
__device__ __half g_xh[MTOT*D_MODEL];            // x as half
__device__ __half g_wqkvT[NQKV*D_MODEL];         // w_qkv^T as half
__device__ __half g_woutT[D_MODEL*D_MODEL];      // w_out^T as half

// ---------------- helpers ---------------------------------------------------
__device__ __forceinline__ uint32_t smem_u32(const void* p) {
    uint32_t a;
    asm("{ .reg .u64 t; cvta.to.shared.u64 t, %1; cvt.u32.u64 %0, t; }" : "=r"(a) : "l"(p));
    return a;
}
__device__ __forceinline__ uint32_t h2pack(float lo, float hi) {
    __half2 h = __floats2half2_rn(lo, hi);
    return *(uint32_t*)&h;
}
__device__ __forceinline__ void mma16(float* c,
    uint32_t a0, uint32_t a1, uint32_t a2, uint32_t a3,
    uint32_t b0, uint32_t b1)
{
    asm volatile(
        "mma.sync.aligned.m16n8k16.row.col.f32.f16.f16.f32 "
        "{%0,%1,%2,%3}, {%4,%5,%6,%7}, {%8,%9}, {%0,%1,%2,%3};"
        : "+f"(c[0]), "+f"(c[1]), "+f"(c[2]), "+f"(c[3])
        : "r"(a0), "r"(a1), "r"(a2), "r"(a3), "r"(b0), "r"(b1));
}
__device__ __forceinline__ void ldm_x4(uint32_t* r, uint32_t addr) {
    asm volatile("ldmatrix.sync.aligned.m8n8.x4.shared.b16 {%0,%1,%2,%3}, [%4];"
        : "=r"(r[0]), "=r"(r[1]), "=r"(r[2]), "=r"(r[3]) : "r"(addr));
}
__device__ __forceinline__ void cp16(uint32_t dst, const void* src) {
    asm volatile("cp.async.cg.shared.global [%0], [%1], 16;" :: "r"(dst), "l"(src));
}
#define CP_COMMIT() asm volatile("cp.async.commit_group;" ::: "memory")
#define CP_WAIT(n)  asm volatile("cp.async.wait_group %0;" :: "n"(n) : "memory")

// ===========================================================================
// Merged pre-pass: one launch does x->half, w_qkv^T->half, w_out^T->half.
// Block ranges:
//   [0, XBLK)            : x cvt (each thread converts 2 float4)
//   [XBLK, XBLK+QT)      : w_qkv transpose tiles (96 x 32)
//   [XBLK+QT, +OT)       : w_out transpose tiles (32 x 32)
// ===========================================================================
#define XBLK 2048                      // (4096*1024/4) / 256 / 2
#define QT_X 96
#define QT_Y 32
#define OT_X 32
#define OT_Y 32
#define PRE_BLOCKS (XBLK + QT_X*QT_Y + OT_X*OT_Y)   // 6144

__global__ __launch_bounds__(256) void prepass_kernel(
    const float* __restrict__ x,
    const float* __restrict__ w_qkv,
    const float* __restrict__ w_out)
{
    __shared__ float t[32][33];
    int b = blockIdx.x;
    if (b < XBLK) {
        const float4* src = (const float4*)x;
        uint2* dst = (uint2*)g_xh;
        int i = b*512 + threadIdx.x;
        #pragma unroll
        for (int r = 0; r < 2; r++) {
            float4 v = src[i + r*256];
            dst[i + r*256] = make_uint2(h2pack(v.x, v.y), h2pack(v.z, v.w));
        }
        return;
    }
    const float* src;
    __half* dst;
    int bx, by, R, C;
    if (b < XBLK + QT_X*QT_Y) {
        int tb = b - XBLK;
        bx = (tb % QT_X) * 32; by = (tb / QT_X) * 32;
        src = w_qkv; dst = g_wqkvT; R = D_MODEL; C = NQKV;
    } else {
        int tb = b - XBLK - QT_X*QT_Y;
        bx = (tb % OT_X) * 32; by = (tb / OT_X) * 32;
        src = w_out; dst = g_woutT; R = D_MODEL; C = D_MODEL;
    }
    int tx = threadIdx.x & 31;
    int ty = threadIdx.x >> 5;
    #pragma unroll
    for (int i = 0; i < 32; i += 8)
        t[ty + i][tx] = src[(size_t)(by + ty + i)*C + bx + tx];
    __syncthreads();
    #pragma unroll
    for (int i = 0; i < 32; i += 8)
        dst[(size_t)(bx + ty + i)*R + by + tx] = __float2half(t[tx][ty + i]);
}

// ===========================================================================
// fp16 MMA GEMM: CTA 128x128, 256 threads (8 warps, warp tile 64x32).
// K chunk 64 halves, 3-stage cp.async, ldmatrix fragments, ONE sync/chunk.
// Stage: A 128 rows x 144B + B 128 rows x 144B = 36864B; 3 stages = 110592B.
// ===========================================================================
#define G_ROW_B 144
#define G_STAGE_BYTES 36864
#define GEMM_SMEM_BYTES (3*G_STAGE_BYTES)   // 110592
#define NCHUNKS (D_MODEL/64)                // 16

__device__ __forceinline__ void gemm_issue(
    uint32_t smem_u, int st,
    const __half* __restrict__ A, const __half* __restrict__ B,
    int m0, int n0, int k0, int tid)
{
    uint32_t sa = smem_u + st*G_STAGE_BYTES;
    uint32_t sb = sa + 128*G_ROW_B;
    const int row = tid >> 3;          // 0..31 (+32*i)
    const int c8  = tid & 7;           // 0..7
    #pragma unroll
    for (int i = 0; i < 4; i++) {
        int r = i*32 + row;
        cp16(sa + r*G_ROW_B + c8*16, A + (size_t)(m0+r)*D_MODEL + k0 + c8*8);
    }
    #pragma unroll
    for (int i = 0; i < 4; i++) {
        int r = i*32 + row;
        cp16(sb + r*G_ROW_B + c8*16, B + (size_t)(n0+r)*D_MODEL + k0 + c8*8);
    }
}

__device__ __forceinline__ void gemm_tile_h(
    uint32_t smem_u,
    const __half* __restrict__ A, const __half* __restrict__ B,
    int m0, int n0, float acc[4][4][4])
{
    const int tid  = threadIdx.x;
    const int lane = tid & 31;
    const int wid  = tid >> 5;
    const int wm   = wid & 1;
    const int wn   = wid >> 1;

    // A tiles ordered (r,k0),(r+8,k0),(r,k8),(r+8,k8)
    const uint32_t aOff = (uint32_t)(wm*64 + (lane & 7) + ((lane >> 3) & 1)*8)*G_ROW_B
                        + ((lane >> 4) & 1)*16;
    // B tiles ordered (n,k0),(n,k8),(n+8,k0),(n+8,k8)
    const uint32_t bOff = 128*G_ROW_B
                        + (uint32_t)(wn*32 + (lane & 7) + ((lane >> 4) & 1)*8)*G_ROW_B
                        + ((lane >> 3) & 1)*16;

    gemm_issue(smem_u, 0, A, B, m0, n0, 0,  tid); CP_COMMIT();
    gemm_issue(smem_u, 1, A, B, m0, n0, 64, tid); CP_COMMIT();

    for (int s = 0; s < NCHUNKS; s++) {
        CP_WAIT(1);
        __syncthreads();
        // Safe single-barrier pipeline: stage written below is (s+2)%3 ==
        // (s-1)%3, whose readers all finished before passing the barrier above.
        if (s + 2 < NCHUNKS) {
            gemm_issue(smem_u, (s+2)%3, A, B, m0, n0, (s+2)*64, tid);
            CP_COMMIT();
        }
        const uint32_t base = smem_u + (s%3)*G_STAGE_BYTES;

        #pragma unroll
        for (int ks = 0; ks < 4; ks++) {          // four k16 steps per chunk
            uint32_t a[4][4], b[2][4];
            #pragma unroll
            for (int mt = 0; mt < 4; mt++)
                ldm_x4(a[mt], base + aOff + mt*(16*G_ROW_B) + ks*32);
            #pragma unroll
            for (int np = 0; np < 2; np++)
                ldm_x4(b[np], base + bOff + np*(16*G_ROW_B) + ks*32);
            #pragma unroll
            for (int nt = 0; nt < 4; nt++) {
                uint32_t b0 = b[nt >> 1][(nt & 1)*2];
                uint32_t b1 = b[nt >> 1][(nt & 1)*2 + 1];
                #pragma unroll
                for (int mt = 0; mt < 4; mt++)
                    mma16(acc[mt][nt], a[mt][0], a[mt][1], a[mt][2], a[mt][3], b0, b1);
            }
        }
    }
}

// ---- GEMM 1: qkv = x @ w_qkv + b, scatter to half q(scaled)/k/vT -----------
__global__ __launch_bounds__(256,2) void qkv_mma_kernel(const float* __restrict__ bias)
{
    extern __shared__ uint32_t smg[];
    uint32_t smem_u = smem_u32(smg);

    const int n0 = blockIdx.x * 128;
    const int m0 = blockIdx.y * 128;
    const int lane = threadIdx.x & 31;
    const int wid  = threadIdx.x >> 5;
    const int wm = wid & 1, wn = wid >> 1;
    const int lq = lane & 3, gq = lane >> 2;

    float acc[4][4][4];
    #pragma unroll
    for (int i = 0; i < 4; i++)
        #pragma unroll
        for (int j = 0; j < 4; j++)
            #pragma unroll
            for (int k = 0; k < 4; k++) acc[i][j][k] = 0.f;

    gemm_tile_h(smem_u, g_xh, g_wqkvT, m0, n0, acc);

    const float QSCALE = 0.125f * 1.4426950408889634f;

    #pragma unroll
    for (int mt = 0; mt < 4; mt++) {
        int rbase = m0 + wm*64 + mt*16 + gq;
        #pragma unroll
        for (int half_ = 0; half_ < 2; half_++) {
            int row = rbase + half_*8;
            int bb = row >> 11;
            int t  = row & 2047;
            #pragma unroll
            for (int nt = 0; nt < 4; nt++) {
                int n = n0 + wn*32 + nt*8 + lq*2;
                float v0 = acc[mt][nt][half_*2+0] + __ldg(bias + n);
                float v1 = acc[mt][nt][half_*2+1] + __ldg(bias + n + 1);
                int sec = n >> 10;
                int h   = (n >> 6) & 15;
                int d   = n & 63;
                int bh  = bb*NHEAD + h;
                if (sec == 0) {
                    *(uint32_t*)&g_qh[((size_t)bh*SEQ + t)*HDIM + d] =
                        h2pack(v0*QSCALE, v1*QSCALE);
                } else if (sec == 1) {
                    *(uint32_t*)&g_kh[((size_t)bh*SEQ + t)*HDIM + d] = h2pack(v0, v1);
                } else {
                    g_vT[((size_t)bh*HDIM + d    )*SEQ + t] = __float2half(v0);
                    g_vT[((size_t)bh*HDIM + d + 1)*SEQ + t] = __float2half(v1);
                }
            }
        }
    }
}

// ---- GEMM 3: out = attn @ w_out + b (f32 output) ----------------------------
__global__ __launch_bounds__(256,2) void out_mma_kernel(
    const float* __restrict__ bias, float* __restrict__ out)
{
    extern __shared__ uint32_t smg[];
    uint32_t smem_u = smem_u32(smg);

    const int n0 = blockIdx.x * 128;
    const int m0 = blockIdx.y * 128;
    const int lane = threadIdx.x & 31;
    const int wid  = threadIdx.x >> 5;
    const int wm = wid & 1, wn = wid >> 1;
    const int lq = lane & 3, gq = lane >> 2;

    float acc[4][4][4];
    #pragma unroll
    for (int i = 0; i < 4; i++)
        #pragma unroll
        for (int j = 0; j < 4; j++)
            #pragma unroll
            for (int k = 0; k < 4; k++) acc[i][j][k] = 0.f;

    gemm_tile_h(smem_u, g_attnh, g_woutT, m0, n0, acc);

    #pragma unroll
    for (int mt = 0; mt < 4; mt++) {
        int rbase = m0 + wm*64 + mt*16 + gq;
        #pragma unroll
        for (int half_ = 0; half_ < 2; half_++) {
            int row = rbase + half_*8;
            #pragma unroll
            for (int nt = 0; nt < 4; nt++) {
                int n = n0 + wn*32 + nt*8 + lq*2;
                float v0 = acc[mt][nt][half_*2+0] + __ldg(bias + n);
                float v1 = acc[mt][nt][half_*2+1] + __ldg(bias + n + 1);
                *(float2*)&out[(size_t)row*D_MODEL + n] = make_float2(v0, v1);
            }
        }
    }
}

// ===========================================================================
// Flash attention, fp16 MMA + ldmatrix (frozen — ~95%+ of HMMA f32acc ceiling)
#define QTILE 128
#define KTILE 64
#define KV_ROW_B 144
#define FL_BUF_BYTES 18432
#define FLASH_SMEM_BYTES (3*FL_BUF_BYTES)     // 55296

__device__ __forceinline__ void flash_issue_kv(
    uint32_t smem_u, int bufidx, int kt,
    const __half* __restrict__ kb, const __half* __restrict__ vT, int tid)
{
    uint32_t kdst = smem_u + bufidx*FL_BUF_BYTES;
    uint32_t vdst = kdst + 64*KV_ROW_B;
    #pragma unroll
    for (int i = 0; i < 2; i++) {
        int idx = tid + i*256;
        int row = idx >> 3, c8 = idx & 7;
        cp16(kdst + row*KV_ROW_B + c8*16,
             kb + ((size_t)kt*KTILE + row)*HDIM + c8*8);
    }
    #pragma unroll
    for (int i = 0; i < 2; i++) {
        int idx = tid + i*256;
        int dh = idx >> 3, c8 = idx & 7;
        cp16(vdst + dh*KV_ROW_B + c8*16,
             vT + (size_t)dh*SEQ + kt*KTILE + c8*8);
    }
}

__global__ __launch_bounds__(256,2) void flash_mma_kernel()
{
    extern __shared__ uint32_t smu[];
    uint32_t smem_u = smem_u32(smu);

    const int tid  = threadIdx.x;
    const int lane = tid & 31;
    const int wid  = tid >> 5;
    const int lq   = lane & 3;
    const int gq   = lane >> 2;

    const int qt = blockIdx.x;
    const int h  = blockIdx.y;
    const int bb = blockIdx.z;
    const int bh = bb*NHEAD + h;

    const __half* qb = g_qh + ((size_t)bh*SEQ + qt*QTILE)*HDIM;
    const __half* kb = g_kh + (size_t)bh*SEQ*HDIM;
    const __half* vT = g_vT + (size_t)bh*HDIM*SEQ;

    flash_issue_kv(smem_u, 0, 0, kb, vT, tid); CP_COMMIT();
    flash_issue_kv(smem_u, 1, 1, kb, vT, tid); CP_COMMIT();

    const int row0 = wid*16 + gq;
    const int row1 = row0 + 8;

    const uint32_t bOff = (uint32_t)((lane & 7) + ((lane >> 4) & 1)*8)*KV_ROW_B
                        + ((lane >> 3) & 1)*16;

    const uint32_t* qu = (const uint32_t*)qb;
    uint32_t qa[4][4];
    #pragma unroll
    for (int kk = 0; kk < 4; kk++) {
        qa[kk][0] = qu[ row0*32 + kk*8 + lq    ];
        qa[kk][1] = qu[ row1*32 + kk*8 + lq    ];
        qa[kk][2] = qu[ row0*32 + kk*8 + lq + 4];
        qa[kk][3] = qu[ row1*32 + kk*8 + lq + 4];
    }

    float m0 = -1e30f, m1 = -1e30f, l0 = 0.f, l1 = 0.f;
    float o[8][4];
    #pragma unroll
    for (int i = 0; i < 8; i++)
        #pragma unroll
        for (int j = 0; j < 4; j++) o[i][j] = 0.f;

    for (int kt = 0; kt < SEQ/KTILE; kt++) {
        CP_WAIT(1);
        __syncthreads();
        if (kt + 2 < SEQ/KTILE) {
            flash_issue_kv(smem_u, (kt+2)%3, kt+2, kb, vT, tid);
            CP_COMMIT();
        }
        const uint32_t kBase = smem_u + (kt%3)*FL_BUF_BYTES;
        const uint32_t vBase = kBase + 64*KV_ROW_B;

        float s[8][4];
        #pragma unroll
        for (int nt = 0; nt < 8; nt++)
            #pragma unroll
            for (int j = 0; j < 4; j++) s[nt][j] = 0.f;

        #pragma unroll
        for (int kk = 0; kk < 4; kk++) {
            uint32_t b[4][4];
            #pragma unroll
            for (int np = 0; np < 4; np++)
                ldm_x4(b[np], kBase + bOff + np*(16*KV_ROW_B) + kk*32);
            #pragma unroll
            for (int nt = 0; nt < 8; nt++) {
                uint32_t b0 = b[nt >> 1][(nt & 1)*2];
                uint32_t b1 = b[nt >> 1][(nt & 1)*2 + 1];
                mma16(s[nt], qa[kk][0], qa[kk][1], qa[kk][2], qa[kk][3], b0, b1);
            }
        }

        float mt0 = -1e30f, mt1 = -1e30f;
        #pragma unroll
        for (int nt = 0; nt < 8; nt++) {
            mt0 = fmaxf(mt0, fmaxf(s[nt][0], s[nt][1]));
            mt1 = fmaxf(mt1, fmaxf(s[nt][2], s[nt][3]));
        }
        mt0 = fmaxf(mt0, __shfl_xor_sync(0xffffffffu, mt0, 1));
        mt0 = fmaxf(mt0, __shfl_xor_sync(0xffffffffu, mt0, 2));
        mt1 = fmaxf(mt1, __shfl_xor_sync(0xffffffffu, mt1, 1));
        mt1 = fmaxf(mt1, __shfl_xor_sync(0xffffffffu, mt1, 2));

        float mn0 = fmaxf(m0, mt0);
        float mn1 = fmaxf(m1, mt1);
        float corr0 = exp2f(m0 - mn0);
        float corr1 = exp2f(m1 - mn1);
        m0 = mn0; m1 = mn1;

        float p[8][4];
        float sum0 = 0.f, sum1 = 0.f;
        #pragma unroll
        for (int nt = 0; nt < 8; nt++) {
            p[nt][0] = exp2f(s[nt][0] - mn0);
            p[nt][1] = exp2f(s[nt][1] - mn0);
            p[nt][2] = exp2f(s[nt][2] - mn1);
            p[nt][3] = exp2f(s[nt][3] - mn1);
            sum0 += p[nt][0] + p[nt][1];
            sum1 += p[nt][2] + p[nt][3];
        }
        sum0 += __shfl_xor_sync(0xffffffffu, sum0, 1);
        sum0 += __shfl_xor_sync(0xffffffffu, sum0, 2);
        sum1 += __shfl_xor_sync(0xffffffffu, sum1, 1);
        sum1 += __shfl_xor_sync(0xffffffffu, sum1, 2);
        l0 = l0*corr0 + sum0;
        l1 = l1*corr1 + sum1;

        #pragma unroll
        for (int nt = 0; nt < 8; nt++) {
            o[nt][0] *= corr0; o[nt][1] *= corr0;
            o[nt][2] *= corr1; o[nt][3] *= corr1;
        }

        #pragma unroll
        for (int kk = 0; kk < 4; kk++) {
            uint32_t a0 = h2pack(p[2*kk  ][0], p[2*kk  ][1]);
            uint32_t a1 = h2pack(p[2*kk  ][2], p[2*kk  ][3]);
            uint32_t a2 = h2pack(p[2*kk+1][0], p[2*kk+1][1]);
            uint32_t a3 = h2pack(p[2*kk+1][2], p[2*kk+1][3]);
            uint32_t b[4][4];
            #pragma unroll
            for (int np = 0; np < 4; np++)
                ldm_x4(b[np], vBase + bOff + np*(16*KV_ROW_B) + kk*32);
            #pragma unroll
            for (int nt = 0; nt < 8; nt++) {
                uint32_t b0 = b[nt >> 1][(nt & 1)*2];
                uint32_t b1 = b[nt >> 1][(nt & 1)*2 + 1];
                mma16(o[nt], a0, a1, a2, a3, b0, b1);
            }
        }
    }

    float inv0 = 1.0f / l0;
    float inv1 = 1.0f / l1;
    #pragma unroll
    for (int nt = 0; nt < 8; nt++) {
        int d = nt*8 + lq*2;
        size_t r0g = (size_t)(bb*SEQ + qt*QTILE + row0)*D_MODEL + h*64 + d;
        size_t r1g = (size_t)(bb*SEQ + qt*QTILE + row1)*D_MODEL + h*64 + d;
        *(uint32_t*)&g_attnh[r0g] = h2pack(o[nt][0]*inv0, o[nt][1]*inv0);
        *(uint32_t*)&g_attnh[r1g] = h2pack(o[nt][2]*inv1, o[nt][3]*inv1);
    }
}

// ===========================================================================
extern "C" void kernel_launch(void* const* d_in, const int* in_sizes, int n_in,
                              void* d_out, int out_size)
{
    const float* x     = (const float*)d_in[0];
    const float* w_qkv = (const float*)d_in[1];
    const float* b_qkv = (const float*)d_in[2];
    const float* w_out = (const float*)d_in[3];
    const float* b_out = (const float*)d_in[4];
    float* out = (float*)d_out;

    (void)in_sizes; (void)n_in; (void)out_size;

    cudaFuncSetAttribute(qkv_mma_kernel,
                         cudaFuncAttributeMaxDynamicSharedMemorySize, GEMM_SMEM_BYTES);
    cudaFuncSetAttribute(out_mma_kernel,
                         cudaFuncAttributeMaxDynamicSharedMemorySize, GEMM_SMEM_BYTES);
    cudaFuncSetAttribute(flash_mma_kernel,
                         cudaFuncAttributeMaxDynamicSharedMemorySize, FLASH_SMEM_BYTES);

    // 0) merged pre-pass: x cvt + both weight transposes, one launch
    prepass_kernel<<<PRE_BLOCKS, 256>>>(x, w_qkv, w_out);

    // 1) QKV GEMM (fp16 MMA + ldmatrix, k64 3-stage)
    {
        dim3 grid(NQKV/128, MTOT/128);
        qkv_mma_kernel<<<grid, 256, GEMM_SMEM_BYTES>>>(b_qkv);
    }
    // 2) flash attention (fp16 MMA + ldmatrix)
    {
        dim3 grid(SEQ/QTILE, NHEAD, BATCH);
        flash_mma_kernel<<<grid, 256, FLASH_SMEM_BYTES>>>();
    }
    // 3) out GEMM (fp16 MMA + ldmatrix, k64 3-stage)
    {
        dim3 grid(D_MODEL/128, MTOT/128);
        out_mma_kernel<<<grid, 256, GEMM_SMEM_BYTES>>>(b_out, out);
    }
}